// round 12
// baseline (speedup 1.0000x reference)
#include <cuda_runtime.h>
#include <math.h>
#include <stdint.h>

#define S_LEN    2048
#define D_MODEL  1024
#define N_HEADS  16
#define HEAD_DIM 64
#define BATCH    2
#define NTOK     (BATCH * S_LEN)   // 4096

// -------- scratch (device globals: no allocations allowed) --------
__device__ float g_Q[NTOK * D_MODEL];             // row-major (RoPE'd, scaled)
__device__ float g_Kf[NTOK * D_MODEL];            // K in attention B-frag order
__device__ float g_Vf[NTOK * D_MODEL];            // V in attention B-frag order
__device__ float g_C[NTOK * D_MODEL];
__device__ float g_Xp[NTOK * D_MODEL];            // x, tf32-rounded, A-frag order
__device__ float g_Wp[4][D_MODEL * D_MODEL];      // weights, tf32-rounded, B-frag order
__device__ float g_cos[S_LEN * 32];
__device__ float g_sin[S_LEN * 32];

#define LOG2E 1.4426950408889634f

__device__ __forceinline__ unsigned f2tf(float x) {
    unsigned u;
    asm("cvt.rna.tf32.f32 %0, %1;" : "=r"(u) : "f"(x));
    return u;
}
__device__ __forceinline__ float f2tff(float x) { return __uint_as_float(f2tf(x)); }

__device__ __forceinline__ void mma8(float c[4], const unsigned a[4],
                                     unsigned b0, unsigned b1) {
    asm volatile(
        "mma.sync.aligned.m16n8k8.row.col.f32.tf32.tf32.f32 "
        "{%0,%1,%2,%3},{%4,%5,%6,%7},{%8,%9},{%0,%1,%2,%3};"
        : "+f"(c[0]), "+f"(c[1]), "+f"(c[2]), "+f"(c[3])
        : "r"(a[0]), "r"(a[1]), "r"(a[2]), "r"(a[3]), "r"(b0), "r"(b1));
}

// K-frag global offset for (token, dim):  per (b,h,tile) 4096-float block,
// [kcp(4)][nt(8)][lane(32)] float4, element e = (dim%16)/4
__device__ __forceinline__ size_t kf_index(int tok, int dim) {
    int b = tok >> 11, s = tok & 2047, tile = s >> 6, sl = s & 63;
    int h = dim >> 6, dl = dim & 63;
    size_t base = ((size_t)(b * N_HEADS + h) * 32 + tile) * 4096;
    int kcp = dl >> 4, e = (dl >> 2) & 3, tg = dl & 3;
    int nt = sl >> 3, gg = sl & 7;
    return base + (size_t)(((kcp * 8 + nt) * 32 + gg * 4 + tg) * 4 + e);
}
// V-frag: token supplies (kcp,e,tig), dim supplies (nt,g)
__device__ __forceinline__ size_t vf_index(int tok, int dim) {
    int b = tok >> 11, s = tok & 2047, tile = s >> 6, sl = s & 63;
    int h = dim >> 6, dl = dim & 63;
    size_t base = ((size_t)(b * N_HEADS + h) * 32 + tile) * 4096;
    int kcp = sl >> 4, e = (sl >> 2) & 3, tg = sl & 3;
    int nt = dl >> 3, gg = dl & 7;
    return base + (size_t)(((kcp * 8 + nt) * 32 + gg * 4 + tg) * 4 + e);
}

// =================================================================
// Preround + permute x (A-frag) and weights (B-frag)  [R11 passing]
// =================================================================
__global__ void preround_permute_kernel(const float* __restrict__ x,
                                        const float* __restrict__ Wq,
                                        const float* __restrict__ Wk,
                                        const float* __restrict__ Wv,
                                        const float* __restrict__ Wo)
{
    const int NXq = NTOK * (D_MODEL / 4);
    const int NWq = D_MODEL * (D_MODEL / 4);
    int idx = blockIdx.x * blockDim.x + threadIdx.x;
    if (idx < NXq) {
        int m = idx >> 8, k4 = idx & 255;
        float4 v = *(const float4*)&x[(size_t)m * D_MODEL + k4 * 4];
        int m_tile = m >> 7, mrow = m & 127;
        int mt = mrow >> 4, r8 = (mrow >> 3) & 1, g = mrow & 7;
        int stage = k4 >> 2, ks = (k4 >> 1) & 1, e4 = k4 & 1;
        int j = r8 + 2 * e4;
        float* base = g_Xp + ((((size_t)m_tile * 64 + stage) * 2 + ks) * 8 + mt) * 128;
        base[(g * 4 + 0) * 4 + j] = f2tff(v.x);
        base[(g * 4 + 1) * 4 + j] = f2tff(v.y);
        base[(g * 4 + 2) * 4 + j] = f2tff(v.z);
        base[(g * 4 + 3) * 4 + j] = f2tff(v.w);
    } else if (idx < NXq + 4 * NWq) {
        int r = idx - NXq;
        int w = r / NWq; r -= w * NWq;
        int n = r >> 8, k4 = r & 255;
        const float* ws[4] = {Wq, Wk, Wv, Wo};
        float4 v = *(const float4*)&ws[w][(size_t)n * D_MODEL + k4 * 4];
        int n_tile = n >> 7, nrow = n & 127;
        int nt = nrow >> 3, g = nrow & 7;
        int stage = k4 >> 2, ks = (k4 >> 1) & 1, j = k4 & 1;
        float* base = g_Wp[w] + ((((size_t)n_tile * 64 + stage) * 2 + ks) * 16 + nt) * 64;
        base[(g * 4 + 0) * 2 + j] = f2tff(v.x);
        base[(g * 4 + 1) * 2 + j] = f2tff(v.y);
        base[(g * 4 + 2) * 2 + j] = f2tff(v.z);
        base[(g * 4 + 3) * 2 + j] = f2tff(v.w);
    }
}

// =================================================================
// RoPE table
// =================================================================
__global__ void rope_table_kernel()
{
    int i = blockIdx.x * blockDim.x + threadIdx.x;
    if (i >= S_LEN * 32) return;
    int pos = i >> 5;
    int f   = i & 31;
    float e    = (float)(2 * f) / 64.0f;
    float pw   = powf(10000.0f, e);
    float invf = 1.0f / pw;
    float angf = (float)pos * invf;
    double s, c;
    sincos((double)angf, &s, &c);
    g_cos[i] = (float)c;
    g_sin[i] = (float)s;
}

// =================================================================
// QKV GEMM (frag-order operands). z=0: Q row-major (+RoPE,scale).
// z=1: K -> g_Kf frag order (+RoPE). z=2: V -> g_Vf frag order.
// =================================================================
__global__ __launch_bounds__(128, 2) void qkv_gemm_kernel()
{
    __shared__ __align__(16) float As[3][2048];
    __shared__ __align__(16) float Bs[3][2048];

    const int z = blockIdx.z;
    const int t = threadIdx.x, warp = t >> 5, lane = t & 31;
    const int g = lane >> 2, tig = lane & 3;
    const int mtb = (warp >> 1) * 4;
    const int ntb = (warp & 1) * 8;
    const int mb = blockIdx.y * 128, nb = blockIdx.x * 128;

    const float* Ag = g_Xp + (size_t)blockIdx.y * 64 * 2048;
    const float* Bg = g_Wp[z] + (size_t)blockIdx.x * 64 * 2048;

    const int rope_mode = (z < 2) ? 1 : 0;
    const float scale = (z == 0) ? 0.125f * LOG2E : 1.0f;

    float acc[4][8][4];
#pragma unroll
    for (int mt = 0; mt < 4; mt++)
#pragma unroll
        for (int nt = 0; nt < 8; nt++)
#pragma unroll
            for (int i = 0; i < 4; i++) acc[mt][nt][i] = 0.f;

#define LOADP(buf, s)                                                              \
    do {                                                                           \
        _Pragma("unroll")                                                          \
        for (int ii = 0; ii < 4; ii++) {                                           \
            int q = t + ii * 128;                                                  \
            unsigned da = (unsigned)__cvta_generic_to_shared(&As[buf][q * 4]);     \
            asm volatile("cp.async.cg.shared.global [%0], [%1], 16;"               \
                         :: "r"(da), "l"(Ag + (size_t)(s) * 2048 + q * 4));        \
            unsigned db = (unsigned)__cvta_generic_to_shared(&Bs[buf][q * 4]);     \
            asm volatile("cp.async.cg.shared.global [%0], [%1], 16;"               \
                         :: "r"(db), "l"(Bg + (size_t)(s) * 2048 + q * 4));        \
        }                                                                          \
        asm volatile("cp.async.commit_group;");                                    \
    } while (0)

    LOADP(0, 0);
    LOADP(1, 1);

    for (int i = 0; i < 64; i++) {
        asm volatile("cp.async.wait_group 1;");
        __syncthreads();
        if (i + 2 < 64) LOADP((i + 2) % 3, i + 2);
        const float* Ab = As[i % 3];
        const float* Bb = Bs[i % 3];

#pragma unroll
        for (int ks = 0; ks < 2; ks++) {
            unsigned af[4][4], bf[8][2];
#pragma unroll
            for (int mt = 0; mt < 4; mt++) {
                float4 a4 = *(const float4*)&Ab[((ks * 8 + mtb + mt) * 32 + lane) * 4];
                af[mt][0] = __float_as_uint(a4.x);
                af[mt][1] = __float_as_uint(a4.y);
                af[mt][2] = __float_as_uint(a4.z);
                af[mt][3] = __float_as_uint(a4.w);
            }
#pragma unroll
            for (int nt = 0; nt < 8; nt++) {
                float2 b2 = *(const float2*)&Bb[((ks * 16 + ntb + nt) * 32 + lane) * 2];
                bf[nt][0] = __float_as_uint(b2.x);
                bf[nt][1] = __float_as_uint(b2.y);
            }
#pragma unroll
            for (int mt = 0; mt < 4; mt++)
#pragma unroll
                for (int nt = 0; nt < 8; nt++)
                    mma8(acc[mt][nt], af[mt], bf[nt][0], bf[nt][1]);
        }
    }

    // ---- epilogue ----
#pragma unroll
    for (int mt = 0; mt < 4; mt++) {
#pragma unroll
        for (int nt = 0; nt < 8; nt++) {
            int row = mb + (warp >> 1) * 64 + mt * 16 + g;
            int col = nb + (warp & 1) * 64 + nt * 8 + 2 * tig;
            float v0 = acc[mt][nt][0], v1 = acc[mt][nt][1];
            float v2 = acc[mt][nt][2], v3 = acc[mt][nt][3];
            if (rope_mode) {
                int fi = (col & 63) >> 1;
                int p0 = row & (S_LEN - 1);
                int p1 = (row + 8) & (S_LEN - 1);
                float c0 = g_cos[p0 * 32 + fi], s0 = g_sin[p0 * 32 + fi];
                float c1 = g_cos[p1 * 32 + fi], s1 = g_sin[p1 * 32 + fi];
                float r0 = v0 * c0 - v1 * s0, r1 = v0 * s0 + v1 * c0;
                float r2 = v2 * c1 - v3 * s1, r3 = v2 * s1 + v3 * c1;
                v0 = r0 * scale; v1 = r1 * scale;
                v2 = r2 * scale; v3 = r3 * scale;
            }
            v0 = f2tff(v0); v1 = f2tff(v1);
            v2 = f2tff(v2); v3 = f2tff(v3);
            if (z == 0) {
                *(float2*)&g_Q[(size_t)row * D_MODEL + col] = make_float2(v0, v1);
                *(float2*)&g_Q[(size_t)(row + 8) * D_MODEL + col] = make_float2(v2, v3);
            } else if (z == 1) {
                g_Kf[kf_index(row, col)]         = v0;
                g_Kf[kf_index(row, col + 1)]     = v1;
                g_Kf[kf_index(row + 8, col)]     = v2;
                g_Kf[kf_index(row + 8, col + 1)] = v3;
            } else {
                g_Vf[vf_index(row, col)]         = v0;
                g_Vf[vf_index(row, col + 1)]     = v1;
                g_Vf[vf_index(row + 8, col)]     = v2;
                g_Vf[vf_index(row + 8, col + 1)] = v3;
            }
        }
    }
}

// =================================================================
// Output GEMM: A = g_C row-major, B = Wo frag-order. [R11 passing]
// =================================================================
#define AST 20

__global__ __launch_bounds__(128, 2) void out_gemm_kernel(float* __restrict__ out)
{
    __shared__ __align__(16) float As[3][128 * AST];
    __shared__ __align__(16) float Bs[3][2048];

    const int t = threadIdx.x, warp = t >> 5, lane = t & 31;
    const int g = lane >> 2, tig = lane & 3;
    const int wm = (warp >> 1) * 64;
    const int ntb = (warp & 1) * 8;
    const int mb = blockIdx.y * 128, nb = blockIdx.x * 128;

    const float* A = g_C;
    const float* Bg = g_Wp[3] + (size_t)blockIdx.x * 64 * 2048;

    float acc[4][8][4];
#pragma unroll
    for (int mt = 0; mt < 4; mt++)
#pragma unroll
        for (int nt = 0; nt < 8; nt++)
#pragma unroll
            for (int i = 0; i < 4; i++) acc[mt][nt][i] = 0.f;

    const int lrow = t >> 2, lcol = (t & 3) * 4;

#define LOADO(buf, s)                                                              \
    do {                                                                           \
        _Pragma("unroll")                                                          \
        for (int rr = 0; rr < 4; rr++) {                                           \
            int row = lrow + rr * 32;                                              \
            unsigned da = (unsigned)__cvta_generic_to_shared(                      \
                &As[buf][row * AST + lcol]);                                       \
            asm volatile("cp.async.cg.shared.global [%0], [%1], 16;"               \
                :: "r"(da), "l"(A + (size_t)(mb + row) * D_MODEL + (s) * 16 + lcol)); \
            int q = t + rr * 128;                                                  \
            unsigned db = (unsigned)__cvta_generic_to_shared(&Bs[buf][q * 4]);     \
            asm volatile("cp.async.cg.shared.global [%0], [%1], 16;"               \
                :: "r"(db), "l"(Bg + (size_t)(s) * 2048 + q * 4));                 \
        }                                                                          \
        asm volatile("cp.async.commit_group;");                                    \
    } while (0)

    LOADO(0, 0);
    LOADO(1, 1);

    for (int i = 0; i < 64; i++) {
        asm volatile("cp.async.wait_group 1;");
        __syncthreads();
        if (i + 2 < 64) LOADO((i + 2) % 3, i + 2);
        const float* Ab = As[i % 3];
        const float* Bb = Bs[i % 3];

#pragma unroll
        for (int ks = 0; ks < 2; ks++) {
            const int kb = ks * 8;
            unsigned af[4][4], bf[8][2];
#pragma unroll
            for (int mt = 0; mt < 4; mt++) {
                int r0 = wm + mt * 16 + g;
                af[mt][0] = __float_as_uint(Ab[r0 * AST + kb + tig]);
                af[mt][1] = __float_as_uint(Ab[(r0 + 8) * AST + kb + tig]);
                af[mt][2] = __float_as_uint(Ab[r0 * AST + kb + tig + 4]);
                af[mt][3] = __float_as_uint(Ab[(r0 + 8) * AST + kb + tig + 4]);
            }
#pragma unroll
            for (int nt = 0; nt < 8; nt++) {
                float2 b2 = *(const float2*)&Bb[((ks * 16 + ntb + nt) * 32 + lane) * 2];
                bf[nt][0] = __float_as_uint(b2.x);
                bf[nt][1] = __float_as_uint(b2.y);
            }
#pragma unroll
            for (int mt = 0; mt < 4; mt++)
#pragma unroll
                for (int nt = 0; nt < 8; nt++)
                    mma8(acc[mt][nt], af[mt], bf[nt][0], bf[nt][1]);
        }
    }

#pragma unroll
    for (int mt = 0; mt < 4; mt++) {
#pragma unroll
        for (int nt = 0; nt < 8; nt++) {
            int row = mb + wm + mt * 16 + g;
            int col = nb + (warp & 1) * 64 + nt * 8 + 2 * tig;
            *(float2*)&out[(size_t)row * D_MODEL + col] =
                make_float2(acc[mt][nt][0], acc[mt][nt][1]);
            *(float2*)&out[(size_t)(row + 8) * D_MODEL + col] =
                make_float2(acc[mt][nt][2], acc[mt][nt][3]);
        }
    }
}

// =================================================================
// TF32 flash attention, causal. K/V read from GLOBAL FRAG ORDER:
// staging = contiguous 16KB copies; mainloop = LDS.128 B-frags.
// 128 threads = 4 warps, 32 q-rows/warp.
// =================================================================
#define PST 68
#define KS4_OFF 0
#define VS4_OFF 4096
#define PS_OFF 8192
#define ATT_SMEM5 ((8192 + 128 * PST) * (int)sizeof(float))

__global__ __launch_bounds__(128, 2) void attn_tf32(
    const float* __restrict__ Q, const float* __restrict__ Kf,
    const float* __restrict__ Vf, float* __restrict__ Ctx)
{
    extern __shared__ __align__(16) float sm5[];
    float* Ks4 = sm5 + KS4_OFF;   // [kcp*8+nt][lane] float4
    float* Vs4 = sm5 + VS4_OFF;
    float* Ps  = sm5 + PS_OFF;

    const int t = threadIdx.x, warp = t >> 5, lane = t & 31;
    const int g = lane >> 2, tig = lane & 3;
    const int qb = ((int)gridDim.x - 1 - (int)blockIdx.x) * 128;  // heavy tiles first
    const int h  = blockIdx.y, b = blockIdx.z;
    const int w32 = warp * 32;

    const float* KfB = Kf + (size_t)(b * N_HEADS + h) * 32 * 4096;
    const float* VfB = Vf + (size_t)(b * N_HEADS + h) * 32 * 4096;

    // ---- stage Q (row-major) into Ps rows, pick up A-fragments ----
    const float* Qg = Q + ((size_t)b * S_LEN + qb) * D_MODEL + h * HEAD_DIM;
#pragma unroll
    for (int i = 0; i < 16; i++) {
        int idx = t + i * 128;
        int row = idx >> 4, c4 = (idx & 15) * 4;
        *(float4*)&Ps[row * PST + c4] =
            *(const float4*)&Qg[(size_t)row * D_MODEL + c4];
    }
    __syncthreads();

    unsigned qf[2][8][4];
#pragma unroll
    for (int bb = 0; bb < 2; bb++)
#pragma unroll
        for (int kc = 0; kc < 8; kc++) {
            int rr = w32 + bb * 16 + g;
            qf[bb][kc][0] = __float_as_uint(Ps[rr * PST + kc * 8 + tig]);
            qf[bb][kc][1] = __float_as_uint(Ps[(rr + 8) * PST + kc * 8 + tig]);
            qf[bb][kc][2] = __float_as_uint(Ps[rr * PST + kc * 8 + tig + 4]);
            qf[bb][kc][3] = __float_as_uint(Ps[(rr + 8) * PST + kc * 8 + tig + 4]);
        }

    float m_[2][2], l_[2][2];
    float o[2][8][4];
#pragma unroll
    for (int bb = 0; bb < 2; bb++) {
        m_[bb][0] = -1e30f; m_[bb][1] = -1e30f;
        l_[bb][0] = 0.f;    l_[bb][1] = 0.f;
#pragma unroll
        for (int nt = 0; nt < 8; nt++)
#pragma unroll
            for (int i = 0; i < 4; i++) o[bb][nt][i] = 0.f;
    }

    const int wrow_max = qb + w32 + 31;

    for (int kt = 0; kt <= qb + 64; kt += 64) {
        __syncthreads();   // prev-iter Ks4/Vs4/Ps reads complete
        const float* Kg = KfB + (size_t)(kt >> 6) * 4096;
        const float* Vg = VfB + (size_t)(kt >> 6) * 4096;
#pragma unroll
        for (int i = 0; i < 8; i++) {
            int idx = t + i * 128;   // 0..1023 float4s
            *(float4*)&Ks4[idx * 4] = *(const float4*)&Kg[idx * 4];
            *(float4*)&Vs4[idx * 4] = *(const float4*)&Vg[idx * 4];
        }
        __syncthreads();

        if (kt > wrow_max) continue;

        // ---- S = Q K^T; one LDS.128 feeds 2 kc for both blocks ----
        float s[2][8][4];
#pragma unroll
        for (int nt = 0; nt < 8; nt++) {
            float c0[4] = {0.f, 0.f, 0.f, 0.f};
            float c1[4] = {0.f, 0.f, 0.f, 0.f};
#pragma unroll
            for (int kcp = 0; kcp < 4; kcp++) {
                float4 kf4 = *(const float4*)&Ks4[((kcp * 8 + nt) * 32 + lane) * 4];
                unsigned b0 = __float_as_uint(kf4.x), b1 = __float_as_uint(kf4.y);
                unsigned b2 = __float_as_uint(kf4.z), b3 = __float_as_uint(kf4.w);
                mma8(c0, qf[0][2 * kcp], b0, b1);
                mma8(c0, qf[0][2 * kcp + 1], b2, b3);
                mma8(c1, qf[1][2 * kcp], b0, b1);
                mma8(c1, qf[1][2 * kcp + 1], b2, b3);
            }
#pragma unroll
            for (int i = 0; i < 4; i++) { s[0][nt][i] = c0[i]; s[1][nt][i] = c1[i]; }
        }

        // ---- causal mask + online softmax per block ----
#pragma unroll
        for (int bb = 0; bb < 2; bb++) {
            const int r0 = qb + w32 + bb * 16 + g;
            const int r1 = r0 + 8;
            if (kt + 63 > qb + w32 + bb * 16) {
#pragma unroll
                for (int nt = 0; nt < 8; nt++) {
                    int k0 = kt + nt * 8 + 2 * tig;
                    if (k0 > r0)     s[bb][nt][0] = -1e30f;
                    if (k0 + 1 > r0) s[bb][nt][1] = -1e30f;
                    if (k0 > r1)     s[bb][nt][2] = -1e30f;
                    if (k0 + 1 > r1) s[bb][nt][3] = -1e30f;
                }
            }

            float mx0 = -1e30f, mx1 = -1e30f;
#pragma unroll
            for (int nt = 0; nt < 8; nt++) {
                mx0 = fmaxf(mx0, fmaxf(s[bb][nt][0], s[bb][nt][1]));
                mx1 = fmaxf(mx1, fmaxf(s[bb][nt][2], s[bb][nt][3]));
            }
            mx0 = fmaxf(mx0, __shfl_xor_sync(0xffffffffu, mx0, 1));
            mx0 = fmaxf(mx0, __shfl_xor_sync(0xffffffffu, mx0, 2));
            mx1 = fmaxf(mx1, __shfl_xor_sync(0xffffffffu, mx1, 1));
            mx1 = fmaxf(mx1, __shfl_xor_sync(0xffffffffu, mx1, 2));

            float nm0 = fmaxf(m_[bb][0], mx0), nm1 = fmaxf(m_[bb][1], mx1);
            float a0 = exp2f(m_[bb][0] - nm0), a1 = exp2f(m_[bb][1] - nm1);
            float sum0 = 0.f, sum1 = 0.f;
#pragma unroll
            for (int nt = 0; nt < 8; nt++) {
                s[bb][nt][0] = exp2f(s[bb][nt][0] - nm0);
                s[bb][nt][1] = exp2f(s[bb][nt][1] - nm0);
                s[bb][nt][2] = exp2f(s[bb][nt][2] - nm1);
                s[bb][nt][3] = exp2f(s[bb][nt][3] - nm1);
                sum0 += s[bb][nt][0] + s[bb][nt][1];
                sum1 += s[bb][nt][2] + s[bb][nt][3];
            }
            sum0 += __shfl_xor_sync(0xffffffffu, sum0, 1);
            sum0 += __shfl_xor_sync(0xffffffffu, sum0, 2);
            sum1 += __shfl_xor_sync(0xffffffffu, sum1, 1);
            sum1 += __shfl_xor_sync(0xffffffffu, sum1, 2);

            l_[bb][0] = l_[bb][0] * a0 + sum0;
            l_[bb][1] = l_[bb][1] * a1 + sum1;
            m_[bb][0] = nm0; m_[bb][1] = nm1;
#pragma unroll
            for (int nt = 0; nt < 8; nt++) {
                o[bb][nt][0] *= a0; o[bb][nt][1] *= a0;
                o[bb][nt][2] *= a1; o[bb][nt][3] *= a1;
            }

            // P (tf32) to warp-private Ps rows
#pragma unroll
            for (int nt = 0; nt < 8; nt++) {
                *(float2*)&Ps[(w32 + bb * 16 + g) * PST + nt * 8 + 2 * tig] =
                    make_float2(f2tff(s[bb][nt][0]), f2tff(s[bb][nt][1]));
                *(float2*)&Ps[(w32 + bb * 16 + g + 8) * PST + nt * 8 + 2 * tig] =
                    make_float2(f2tff(s[bb][nt][2]), f2tff(s[bb][nt][3]));
            }
        }
        __syncwarp();

        // ---- O += P @ V; one LDS.128 feeds 2 kc for both blocks ----
#pragma unroll
        for (int kcp = 0; kcp < 4; kcp++) {
            unsigned pf[2][2][4];
#pragma unroll
            for (int bb = 0; bb < 2; bb++) {
                int rr = w32 + bb * 16 + g;
#pragma unroll
                for (int j = 0; j < 2; j++) {
                    int kc = 2 * kcp + j;
                    pf[bb][j][0] = __float_as_uint(Ps[rr * PST + kc * 8 + tig]);
                    pf[bb][j][1] = __float_as_uint(Ps[(rr + 8) * PST + kc * 8 + tig]);
                    pf[bb][j][2] = __float_as_uint(Ps[rr * PST + kc * 8 + tig + 4]);
                    pf[bb][j][3] = __float_as_uint(Ps[(rr + 8) * PST + kc * 8 + tig + 4]);
                }
            }
#pragma unroll
            for (int nt = 0; nt < 8; nt++) {
                float4 vf4 = *(const float4*)&Vs4[((kcp * 8 + nt) * 32 + lane) * 4];
                unsigned b0 = __float_as_uint(vf4.x), b1 = __float_as_uint(vf4.y);
                unsigned b2 = __float_as_uint(vf4.z), b3 = __float_as_uint(vf4.w);
                mma8(o[0][nt], pf[0][0], b0, b1);
                mma8(o[0][nt], pf[0][1], b2, b3);
                mma8(o[1][nt], pf[1][0], b0, b1);
                mma8(o[1][nt], pf[1][1], b2, b3);
            }
        }
        __syncwarp();
    }

    // ---- epilogue ----
#pragma unroll
    for (int bb = 0; bb < 2; bb++) {
        float inv0 = 1.0f / l_[bb][0], inv1 = 1.0f / l_[bb][1];
        float* Cb = Ctx + ((size_t)b * S_LEN + qb + w32 + bb * 16) * D_MODEL
                        + h * HEAD_DIM;
#pragma unroll
        for (int nt = 0; nt < 8; nt++) {
            *(float2*)&Cb[(size_t)g * D_MODEL + nt * 8 + 2 * tig] =
                make_float2(f2tff(o[bb][nt][0] * inv0), f2tff(o[bb][nt][1] * inv0));
            *(float2*)&Cb[(size_t)(g + 8) * D_MODEL + nt * 8 + 2 * tig] =
                make_float2(f2tff(o[bb][nt][2] * inv1), f2tff(o[bb][nt][3] * inv1));
        }
    }
}

// =================================================================
// Launch
// =================================================================
extern "C" void kernel_launch(void* const* d_in, const int* in_sizes, int n_in,
                              void* d_out, int out_size)
{
    const float* x  = (const float*)d_in[0];
    const float* Wq = (const float*)d_in[1];
    const float* Wk = (const float*)d_in[2];
    const float* Wv = (const float*)d_in[3];
    const float* Wo = (const float*)d_in[4];
    float* out = (float*)d_out;

    float *Q, *Kf, *Vf, *C;
    cudaGetSymbolAddress((void**)&Q, g_Q);
    cudaGetSymbolAddress((void**)&Kf, g_Kf);
    cudaGetSymbolAddress((void**)&Vf, g_Vf);
    cudaGetSymbolAddress((void**)&C, g_C);

    // 0: rope table
    rope_table_kernel<<<(S_LEN * 32 + 255) / 256, 256>>>();

    // 1: pre-round + permute x and weights into fragment order
    int nthreads = NTOK * (D_MODEL / 4) + 4 * D_MODEL * (D_MODEL / 4);
    preround_permute_kernel<<<(nthreads + 255) / 256, 256>>>(x, Wq, Wk, Wv, Wo);

    // 2: fused QKV projections; K/V written in attention frag order
    qkv_gemm_kernel<<<dim3(D_MODEL / 128, NTOK / 128, 3), 128>>>();

    // 3: attention (K/V frag-order smem, LDS.128 mainloop)
    cudaFuncSetAttribute(attn_tf32, cudaFuncAttributeMaxDynamicSharedMemorySize, ATT_SMEM5);
    attn_tf32<<<dim3(S_LEN / 128, N_HEADS, BATCH), 128, ATT_SMEM5>>>(Q, Kf, Vf, C);

    // 4: output projection
    out_gemm_kernel<<<dim3(D_MODEL / 128, NTOK / 128), 128>>>(out);
}

// round 13
// speedup vs baseline: 1.0008x; 1.0008x over previous
#include <cuda_runtime.h>
#include <math.h>
#include <stdint.h>

#define S_LEN    2048
#define D_MODEL  1024
#define N_HEADS  16
#define HEAD_DIM 64
#define BATCH    2
#define NTOK     (BATCH * S_LEN)   // 4096

// -------- scratch (device globals: no allocations allowed) --------
__device__ float g_Qf[NTOK * D_MODEL];            // Q in attention A-frag order
__device__ float g_Kf[NTOK * D_MODEL];            // K in attention B-frag order
__device__ float g_Vf[NTOK * D_MODEL];            // V in attention B-frag order
__device__ float g_C[NTOK * D_MODEL];
__device__ float g_Xp[NTOK * D_MODEL];            // x, tf32-rounded, A-frag order
__device__ float g_Wp[4][D_MODEL * D_MODEL];      // weights, tf32-rounded, B-frag order
__device__ float g_cos[S_LEN * 32];
__device__ float g_sin[S_LEN * 32];

#define LOG2E 1.4426950408889634f

__device__ __forceinline__ unsigned f2tf(float x) {
    unsigned u;
    asm("cvt.rna.tf32.f32 %0, %1;" : "=r"(u) : "f"(x));
    return u;
}
__device__ __forceinline__ float f2tff(float x) { return __uint_as_float(f2tf(x)); }

__device__ __forceinline__ void mma8(float c[4], const unsigned a[4],
                                     unsigned b0, unsigned b1) {
    asm volatile(
        "mma.sync.aligned.m16n8k8.row.col.f32.tf32.tf32.f32 "
        "{%0,%1,%2,%3},{%4,%5,%6,%7},{%8,%9},{%0,%1,%2,%3};"
        : "+f"(c[0]), "+f"(c[1]), "+f"(c[2]), "+f"(c[3])
        : "r"(a[0]), "r"(a[1]), "r"(a[2]), "r"(a[3]), "r"(b0), "r"(b1));
}

// ---- local (within 128x128 tile) fragment-layout indices ----
// Q: per-head 8192-float block [w2(4)][bb(2)][kc(8)][lane(32)]x4, j=r8+2*e4
__device__ __forceinline__ int qf_local(int r, int c) {
    int hh = c >> 6, dl = c & 63;
    int w2 = r >> 5, bb = (r >> 4) & 1, g = r & 7, r8 = (r >> 3) & 1;
    int kc = dl >> 3, tig = dl & 3, e4 = (dl >> 2) & 1;
    return hh * 8192 + ((w2 * 2 + bb) * 8 + kc) * 128 + (g * 4 + tig) * 4 + (r8 + 2 * e4);
}
// K: per (head, 64-token tile) 4096-float block [kcp(4)][nt(8)][lane(32)]x4
__device__ __forceinline__ int kf_local(int r, int c) {
    int hh = c >> 6, dl = c & 63, tt = r >> 6, sl = r & 63;
    return (hh * 2 + tt) * 4096 + ((dl >> 4) * 8 + (sl >> 3)) * 128
         + ((sl & 7) * 4 + (dl & 3)) * 4 + ((dl >> 2) & 3);
}
// V: token supplies (kcp,e,tg), dim supplies (nt,g)
__device__ __forceinline__ int vf_local(int r, int c) {
    int hh = c >> 6, dl = c & 63, tt = r >> 6, sl = r & 63;
    return (hh * 2 + tt) * 4096 + ((sl >> 4) * 8 + (dl >> 3)) * 128
         + ((dl & 7) * 4 + (sl & 3)) * 4 + ((sl >> 2) & 3);
}

// =================================================================
// Preround + permute x (A-frag) and weights (B-frag)  [R11 passing]
// =================================================================
__global__ void preround_permute_kernel(const float* __restrict__ x,
                                        const float* __restrict__ Wq,
                                        const float* __restrict__ Wk,
                                        const float* __restrict__ Wv,
                                        const float* __restrict__ Wo)
{
    const int NXq = NTOK * (D_MODEL / 4);
    const int NWq = D_MODEL * (D_MODEL / 4);
    int idx = blockIdx.x * blockDim.x + threadIdx.x;
    if (idx < NXq) {
        int m = idx >> 8, k4 = idx & 255;
        float4 v = *(const float4*)&x[(size_t)m * D_MODEL + k4 * 4];
        int m_tile = m >> 7, mrow = m & 127;
        int mt = mrow >> 4, r8 = (mrow >> 3) & 1, g = mrow & 7;
        int stage = k4 >> 2, ks = (k4 >> 1) & 1, e4 = k4 & 1;
        int j = r8 + 2 * e4;
        float* base = g_Xp + ((((size_t)m_tile * 64 + stage) * 2 + ks) * 8 + mt) * 128;
        base[(g * 4 + 0) * 4 + j] = f2tff(v.x);
        base[(g * 4 + 1) * 4 + j] = f2tff(v.y);
        base[(g * 4 + 2) * 4 + j] = f2tff(v.z);
        base[(g * 4 + 3) * 4 + j] = f2tff(v.w);
    } else if (idx < NXq + 4 * NWq) {
        int r = idx - NXq;
        int w = r / NWq; r -= w * NWq;
        int n = r >> 8, k4 = r & 255;
        const float* ws[4] = {Wq, Wk, Wv, Wo};
        float4 v = *(const float4*)&ws[w][(size_t)n * D_MODEL + k4 * 4];
        int n_tile = n >> 7, nrow = n & 127;
        int nt = nrow >> 3, g = nrow & 7;
        int stage = k4 >> 2, ks = (k4 >> 1) & 1, j = k4 & 1;
        float* base = g_Wp[w] + ((((size_t)n_tile * 64 + stage) * 2 + ks) * 16 + nt) * 64;
        base[(g * 4 + 0) * 2 + j] = f2tff(v.x);
        base[(g * 4 + 1) * 2 + j] = f2tff(v.y);
        base[(g * 4 + 2) * 2 + j] = f2tff(v.z);
        base[(g * 4 + 3) * 2 + j] = f2tff(v.w);
    }
}

// =================================================================
// RoPE table
// =================================================================
__global__ void rope_table_kernel()
{
    int i = blockIdx.x * blockDim.x + threadIdx.x;
    if (i >= S_LEN * 32) return;
    int pos = i >> 5;
    int f   = i & 31;
    float e    = (float)(2 * f) / 64.0f;
    float pw   = powf(10000.0f, e);
    float invf = 1.0f / pw;
    float angf = (float)pos * invf;
    double s, c;
    sincos((double)angf, &s, &c);
    g_cos[i] = (float)c;
    g_sin[i] = (float)s;
}

// =================================================================
// QKV GEMM (frag-order operands), 64KB dynamic smem.
// Mainloop identical to R11. Epilogue: RoPE -> scatter tile into
// frag-layout smem -> coalesced STG.128 to g_Qf/g_Kf/g_Vf.
// =================================================================
#define QKV_SMEM (16384 * 4)   // 64 KB: pipeline (48KB) then staging (64KB)

__global__ __launch_bounds__(128, 2) void qkv_gemm_kernel()
{
    extern __shared__ __align__(16) float smq[];
    float* Asb = smq;            // 3 * 2048
    float* Bsb = smq + 6144;     // 3 * 2048

    const int z = blockIdx.z;
    const int t = threadIdx.x, warp = t >> 5, lane = t & 31;
    const int g = lane >> 2, tig = lane & 3;
    const int mtb = (warp >> 1) * 4;
    const int ntb = (warp & 1) * 8;
    const int mb = blockIdx.y * 128, nb = blockIdx.x * 128;

    const float* Ag = g_Xp + (size_t)blockIdx.y * 64 * 2048;
    const float* Bg = g_Wp[z] + (size_t)blockIdx.x * 64 * 2048;

    const int rope_mode = (z < 2) ? 1 : 0;
    const float scale = (z == 0) ? 0.125f * LOG2E : 1.0f;

    float acc[4][8][4];
#pragma unroll
    for (int mt = 0; mt < 4; mt++)
#pragma unroll
        for (int nt = 0; nt < 8; nt++)
#pragma unroll
            for (int i = 0; i < 4; i++) acc[mt][nt][i] = 0.f;

#define LOADP(buf, s)                                                              \
    do {                                                                           \
        _Pragma("unroll")                                                          \
        for (int ii = 0; ii < 4; ii++) {                                           \
            int q = t + ii * 128;                                                  \
            unsigned da = (unsigned)__cvta_generic_to_shared(                      \
                &Asb[(buf) * 2048 + q * 4]);                                       \
            asm volatile("cp.async.cg.shared.global [%0], [%1], 16;"               \
                         :: "r"(da), "l"(Ag + (size_t)(s) * 2048 + q * 4));        \
            unsigned db = (unsigned)__cvta_generic_to_shared(                      \
                &Bsb[(buf) * 2048 + q * 4]);                                       \
            asm volatile("cp.async.cg.shared.global [%0], [%1], 16;"               \
                         :: "r"(db), "l"(Bg + (size_t)(s) * 2048 + q * 4));        \
        }                                                                          \
        asm volatile("cp.async.commit_group;");                                    \
    } while (0)

    LOADP(0, 0);
    LOADP(1, 1);

    for (int i = 0; i < 64; i++) {
        asm volatile("cp.async.wait_group 1;");
        __syncthreads();
        if (i + 2 < 64) LOADP((i + 2) % 3, i + 2);
        const float* Ab = Asb + (i % 3) * 2048;
        const float* Bb = Bsb + (i % 3) * 2048;

#pragma unroll
        for (int ks = 0; ks < 2; ks++) {
            unsigned af[4][4], bf[8][2];
#pragma unroll
            for (int mt = 0; mt < 4; mt++) {
                float4 a4 = *(const float4*)&Ab[((ks * 8 + mtb + mt) * 32 + lane) * 4];
                af[mt][0] = __float_as_uint(a4.x);
                af[mt][1] = __float_as_uint(a4.y);
                af[mt][2] = __float_as_uint(a4.z);
                af[mt][3] = __float_as_uint(a4.w);
            }
#pragma unroll
            for (int nt = 0; nt < 8; nt++) {
                float2 b2 = *(const float2*)&Bb[((ks * 16 + ntb + nt) * 32 + lane) * 2];
                bf[nt][0] = __float_as_uint(b2.x);
                bf[nt][1] = __float_as_uint(b2.y);
            }
#pragma unroll
            for (int mt = 0; mt < 4; mt++)
#pragma unroll
                for (int nt = 0; nt < 8; nt++)
                    mma8(acc[mt][nt], af[mt], bf[nt][0], bf[nt][1]);
        }
    }

    // ---- epilogue: RoPE + round, scatter to frag-layout smem ----
    __syncthreads();           // everyone done reading pipeline buffers
    float* stg = smq;          // 16384-float staging (64KB)

#pragma unroll
    for (int mt = 0; mt < 4; mt++) {
#pragma unroll
        for (int nt = 0; nt < 8; nt++) {
            int rl = (warp >> 1) * 64 + mt * 16 + g;        // local row 0..127
            int cl = (warp & 1) * 64 + nt * 8 + 2 * tig;    // local col 0..127
            int row = mb + rl;
            float v0 = acc[mt][nt][0], v1 = acc[mt][nt][1];
            float v2 = acc[mt][nt][2], v3 = acc[mt][nt][3];
            if (rope_mode) {
                int fi = (cl & 63) >> 1;
                int p0 = row & (S_LEN - 1);
                int p1 = (row + 8) & (S_LEN - 1);
                float c0 = g_cos[p0 * 32 + fi], s0 = g_sin[p0 * 32 + fi];
                float c1 = g_cos[p1 * 32 + fi], s1 = g_sin[p1 * 32 + fi];
                float r0 = v0 * c0 - v1 * s0, r1 = v0 * s0 + v1 * c0;
                float r2 = v2 * c1 - v3 * s1, r3 = v2 * s1 + v3 * c1;
                v0 = r0 * scale; v1 = r1 * scale;
                v2 = r2 * scale; v3 = r3 * scale;
            }
            v0 = f2tff(v0); v1 = f2tff(v1);
            v2 = f2tff(v2); v3 = f2tff(v3);
            if (z == 0) {
                stg[qf_local(rl, cl)]         = v0;
                stg[qf_local(rl, cl + 1)]     = v1;
                stg[qf_local(rl + 8, cl)]     = v2;
                stg[qf_local(rl + 8, cl + 1)] = v3;
            } else if (z == 1) {
                stg[kf_local(rl, cl)]         = v0;
                stg[kf_local(rl, cl + 1)]     = v1;
                stg[kf_local(rl + 8, cl)]     = v2;
                stg[kf_local(rl + 8, cl + 1)] = v3;
            } else {
                stg[vf_local(rl, cl)]         = v0;
                stg[vf_local(rl, cl + 1)]     = v1;
                stg[vf_local(rl + 8, cl)]     = v2;
                stg[vf_local(rl + 8, cl + 1)] = v3;
            }
        }
    }
    __syncthreads();

    // ---- coalesced copy out ----
    const int bI = mb >> 11;          // batch
    const int h0 = nb >> 6;           // first head of this col-block
    if (z == 0) {
        const int qt = (mb & 2047) >> 7;
#pragma unroll
        for (int hh = 0; hh < 2; hh++) {
            float4* dst = (float4*)(g_Qf + (((size_t)(bI * N_HEADS + h0 + hh)) * 16 + qt) * 8192);
            const float4* src = (const float4*)(stg + hh * 8192);
#pragma unroll
            for (int i = 0; i < 16; i++) dst[t + i * 128] = src[t + i * 128];
        }
    } else {
        float* gdst = (z == 1) ? g_Kf : g_Vf;
        const int kt0 = (mb & 2047) >> 6;
#pragma unroll
        for (int hh = 0; hh < 2; hh++)
#pragma unroll
            for (int tt = 0; tt < 2; tt++) {
                float4* dst = (float4*)(gdst +
                    (((size_t)(bI * N_HEADS + h0 + hh)) * 32 + kt0 + tt) * 4096);
                const float4* src = (const float4*)(stg + (hh * 2 + tt) * 4096);
#pragma unroll
                for (int i = 0; i < 8; i++) dst[t + i * 128] = src[t + i * 128];
            }
    }
}

// =================================================================
// Output GEMM: A = g_C row-major, B = Wo frag-order. [R11 passing]
// =================================================================
#define AST 20

__global__ __launch_bounds__(128, 2) void out_gemm_kernel(float* __restrict__ out)
{
    __shared__ __align__(16) float As[3][128 * AST];
    __shared__ __align__(16) float Bs[3][2048];

    const int t = threadIdx.x, warp = t >> 5, lane = t & 31;
    const int g = lane >> 2, tig = lane & 3;
    const int wm = (warp >> 1) * 64;
    const int ntb = (warp & 1) * 8;
    const int mb = blockIdx.y * 128, nb = blockIdx.x * 128;

    const float* A = g_C;
    const float* Bg = g_Wp[3] + (size_t)blockIdx.x * 64 * 2048;

    float acc[4][8][4];
#pragma unroll
    for (int mt = 0; mt < 4; mt++)
#pragma unroll
        for (int nt = 0; nt < 8; nt++)
#pragma unroll
            for (int i = 0; i < 4; i++) acc[mt][nt][i] = 0.f;

    const int lrow = t >> 2, lcol = (t & 3) * 4;

#define LOADO(buf, s)                                                              \
    do {                                                                           \
        _Pragma("unroll")                                                          \
        for (int rr = 0; rr < 4; rr++) {                                           \
            int row = lrow + rr * 32;                                              \
            unsigned da = (unsigned)__cvta_generic_to_shared(                      \
                &As[buf][row * AST + lcol]);                                       \
            asm volatile("cp.async.cg.shared.global [%0], [%1], 16;"               \
                :: "r"(da), "l"(A + (size_t)(mb + row) * D_MODEL + (s) * 16 + lcol)); \
            int q = t + rr * 128;                                                  \
            unsigned db = (unsigned)__cvta_generic_to_shared(&Bs[buf][q * 4]);     \
            asm volatile("cp.async.cg.shared.global [%0], [%1], 16;"               \
                :: "r"(db), "l"(Bg + (size_t)(s) * 2048 + q * 4));                 \
        }                                                                          \
        asm volatile("cp.async.commit_group;");                                    \
    } while (0)

    LOADO(0, 0);
    LOADO(1, 1);

    for (int i = 0; i < 64; i++) {
        asm volatile("cp.async.wait_group 1;");
        __syncthreads();
        if (i + 2 < 64) LOADO((i + 2) % 3, i + 2);
        const float* Ab = As[i % 3];
        const float* Bb = Bs[i % 3];

#pragma unroll
        for (int ks = 0; ks < 2; ks++) {
            const int kb = ks * 8;
            unsigned af[4][4], bf[8][2];
#pragma unroll
            for (int mt = 0; mt < 4; mt++) {
                int r0 = wm + mt * 16 + g;
                af[mt][0] = __float_as_uint(Ab[r0 * AST + kb + tig]);
                af[mt][1] = __float_as_uint(Ab[(r0 + 8) * AST + kb + tig]);
                af[mt][2] = __float_as_uint(Ab[r0 * AST + kb + tig + 4]);
                af[mt][3] = __float_as_uint(Ab[(r0 + 8) * AST + kb + tig + 4]);
            }
#pragma unroll
            for (int nt = 0; nt < 8; nt++) {
                float2 b2 = *(const float2*)&Bb[((ks * 16 + ntb + nt) * 32 + lane) * 2];
                bf[nt][0] = __float_as_uint(b2.x);
                bf[nt][1] = __float_as_uint(b2.y);
            }
#pragma unroll
            for (int mt = 0; mt < 4; mt++)
#pragma unroll
                for (int nt = 0; nt < 8; nt++)
                    mma8(acc[mt][nt], af[mt], bf[nt][0], bf[nt][1]);
        }
    }

#pragma unroll
    for (int mt = 0; mt < 4; mt++) {
#pragma unroll
        for (int nt = 0; nt < 8; nt++) {
            int row = mb + wm + mt * 16 + g;
            int col = nb + (warp & 1) * 64 + nt * 8 + 2 * tig;
            *(float2*)&out[(size_t)row * D_MODEL + col] =
                make_float2(acc[mt][nt][0], acc[mt][nt][1]);
            *(float2*)&out[(size_t)(row + 8) * D_MODEL + col] =
                make_float2(acc[mt][nt][2], acc[mt][nt][3]);
        }
    }
}

// =================================================================
// TF32 flash attention, causal. Q/K/V all read from GLOBAL FRAG ORDER.
// Q: 16 direct LDG.128 per thread (no smem staging).
// K/V: contiguous 16KB tile copies, LDS.128 mainloop.
// =================================================================
#define PST 68
#define KS4_OFF 0
#define VS4_OFF 4096
#define PS_OFF 8192
#define ATT_SMEM5 ((8192 + 128 * PST) * (int)sizeof(float))

__global__ __launch_bounds__(128, 2) void attn_tf32(
    const float* __restrict__ Qf, const float* __restrict__ Kf,
    const float* __restrict__ Vf, float* __restrict__ Ctx)
{
    extern __shared__ __align__(16) float sm5[];
    float* Ks4 = sm5 + KS4_OFF;
    float* Vs4 = sm5 + VS4_OFF;
    float* Ps  = sm5 + PS_OFF;

    const int t = threadIdx.x, warp = t >> 5, lane = t & 31;
    const int g = lane >> 2, tig = lane & 3;
    const int qb = ((int)gridDim.x - 1 - (int)blockIdx.x) * 128;  // heavy tiles first
    const int h  = blockIdx.y, b = blockIdx.z;
    const int w32 = warp * 32;

    const float* KfB = Kf + (size_t)(b * N_HEADS + h) * 32 * 4096;
    const float* VfB = Vf + (size_t)(b * N_HEADS + h) * 32 * 4096;
    const float* Qblk = Qf + ((size_t)(b * N_HEADS + h) * 16 + (qb >> 7)) * 8192;

    // ---- Q A-fragments: direct coalesced global loads ----
    unsigned qf[2][8][4];
#pragma unroll
    for (int bb = 0; bb < 2; bb++)
#pragma unroll
        for (int kc = 0; kc < 8; kc++) {
            float4 q4 = *(const float4*)&Qblk[(((warp * 2 + bb) * 8 + kc) * 32 + lane) * 4];
            qf[bb][kc][0] = __float_as_uint(q4.x);
            qf[bb][kc][1] = __float_as_uint(q4.y);
            qf[bb][kc][2] = __float_as_uint(q4.z);
            qf[bb][kc][3] = __float_as_uint(q4.w);
        }

    float m_[2][2], l_[2][2];
    float o[2][8][4];
#pragma unroll
    for (int bb = 0; bb < 2; bb++) {
        m_[bb][0] = -1e30f; m_[bb][1] = -1e30f;
        l_[bb][0] = 0.f;    l_[bb][1] = 0.f;
#pragma unroll
        for (int nt = 0; nt < 8; nt++)
#pragma unroll
            for (int i = 0; i < 4; i++) o[bb][nt][i] = 0.f;
    }

    const int wrow_max = qb + w32 + 31;

    for (int kt = 0; kt <= qb + 64; kt += 64) {
        __syncthreads();
        const float* Kg = KfB + (size_t)(kt >> 6) * 4096;
        const float* Vg = VfB + (size_t)(kt >> 6) * 4096;
#pragma unroll
        for (int i = 0; i < 8; i++) {
            int idx = t + i * 128;
            *(float4*)&Ks4[idx * 4] = *(const float4*)&Kg[idx * 4];
            *(float4*)&Vs4[idx * 4] = *(const float4*)&Vg[idx * 4];
        }
        __syncthreads();

        if (kt > wrow_max) continue;

        float s[2][8][4];
#pragma unroll
        for (int nt = 0; nt < 8; nt++) {
            float c0[4] = {0.f, 0.f, 0.f, 0.f};
            float c1[4] = {0.f, 0.f, 0.f, 0.f};
#pragma unroll
            for (int kcp = 0; kcp < 4; kcp++) {
                float4 kf4 = *(const float4*)&Ks4[((kcp * 8 + nt) * 32 + lane) * 4];
                unsigned b0 = __float_as_uint(kf4.x), b1 = __float_as_uint(kf4.y);
                unsigned b2 = __float_as_uint(kf4.z), b3 = __float_as_uint(kf4.w);
                mma8(c0, qf[0][2 * kcp], b0, b1);
                mma8(c0, qf[0][2 * kcp + 1], b2, b3);
                mma8(c1, qf[1][2 * kcp], b0, b1);
                mma8(c1, qf[1][2 * kcp + 1], b2, b3);
            }
#pragma unroll
            for (int i = 0; i < 4; i++) { s[0][nt][i] = c0[i]; s[1][nt][i] = c1[i]; }
        }

#pragma unroll
        for (int bb = 0; bb < 2; bb++) {
            const int r0 = qb + w32 + bb * 16 + g;
            const int r1 = r0 + 8;
            if (kt + 63 > qb + w32 + bb * 16) {
#pragma unroll
                for (int nt = 0; nt < 8; nt++) {
                    int k0 = kt + nt * 8 + 2 * tig;
                    if (k0 > r0)     s[bb][nt][0] = -1e30f;
                    if (k0 + 1 > r0) s[bb][nt][1] = -1e30f;
                    if (k0 > r1)     s[bb][nt][2] = -1e30f;
                    if (k0 + 1 > r1) s[bb][nt][3] = -1e30f;
                }
            }

            float mx0 = -1e30f, mx1 = -1e30f;
#pragma unroll
            for (int nt = 0; nt < 8; nt++) {
                mx0 = fmaxf(mx0, fmaxf(s[bb][nt][0], s[bb][nt][1]));
                mx1 = fmaxf(mx1, fmaxf(s[bb][nt][2], s[bb][nt][3]));
            }
            mx0 = fmaxf(mx0, __shfl_xor_sync(0xffffffffu, mx0, 1));
            mx0 = fmaxf(mx0, __shfl_xor_sync(0xffffffffu, mx0, 2));
            mx1 = fmaxf(mx1, __shfl_xor_sync(0xffffffffu, mx1, 1));
            mx1 = fmaxf(mx1, __shfl_xor_sync(0xffffffffu, mx1, 2));

            float nm0 = fmaxf(m_[bb][0], mx0), nm1 = fmaxf(m_[bb][1], mx1);
            float a0 = exp2f(m_[bb][0] - nm0), a1 = exp2f(m_[bb][1] - nm1);
            float sum0 = 0.f, sum1 = 0.f;
#pragma unroll
            for (int nt = 0; nt < 8; nt++) {
                s[bb][nt][0] = exp2f(s[bb][nt][0] - nm0);
                s[bb][nt][1] = exp2f(s[bb][nt][1] - nm0);
                s[bb][nt][2] = exp2f(s[bb][nt][2] - nm1);
                s[bb][nt][3] = exp2f(s[bb][nt][3] - nm1);
                sum0 += s[bb][nt][0] + s[bb][nt][1];
                sum1 += s[bb][nt][2] + s[bb][nt][3];
            }
            sum0 += __shfl_xor_sync(0xffffffffu, sum0, 1);
            sum0 += __shfl_xor_sync(0xffffffffu, sum0, 2);
            sum1 += __shfl_xor_sync(0xffffffffu, sum1, 1);
            sum1 += __shfl_xor_sync(0xffffffffu, sum1, 2);

            l_[bb][0] = l_[bb][0] * a0 + sum0;
            l_[bb][1] = l_[bb][1] * a1 + sum1;
            m_[bb][0] = nm0; m_[bb][1] = nm1;
#pragma unroll
            for (int nt = 0; nt < 8; nt++) {
                o[bb][nt][0] *= a0; o[bb][nt][1] *= a0;
                o[bb][nt][2] *= a1; o[bb][nt][3] *= a1;
            }

#pragma unroll
            for (int nt = 0; nt < 8; nt++) {
                *(float2*)&Ps[(w32 + bb * 16 + g) * PST + nt * 8 + 2 * tig] =
                    make_float2(f2tff(s[bb][nt][0]), f2tff(s[bb][nt][1]));
                *(float2*)&Ps[(w32 + bb * 16 + g + 8) * PST + nt * 8 + 2 * tig] =
                    make_float2(f2tff(s[bb][nt][2]), f2tff(s[bb][nt][3]));
            }
        }
        __syncwarp();

#pragma unroll
        for (int kcp = 0; kcp < 4; kcp++) {
            unsigned pf[2][2][4];
#pragma unroll
            for (int bb = 0; bb < 2; bb++) {
                int rr = w32 + bb * 16 + g;
#pragma unroll
                for (int j = 0; j < 2; j++) {
                    int kc = 2 * kcp + j;
                    pf[bb][j][0] = __float_as_uint(Ps[rr * PST + kc * 8 + tig]);
                    pf[bb][j][1] = __float_as_uint(Ps[(rr + 8) * PST + kc * 8 + tig]);
                    pf[bb][j][2] = __float_as_uint(Ps[rr * PST + kc * 8 + tig + 4]);
                    pf[bb][j][3] = __float_as_uint(Ps[(rr + 8) * PST + kc * 8 + tig + 4]);
                }
            }
#pragma unroll
            for (int nt = 0; nt < 8; nt++) {
                float4 vf4 = *(const float4*)&Vs4[((kcp * 8 + nt) * 32 + lane) * 4];
                unsigned b0 = __float_as_uint(vf4.x), b1 = __float_as_uint(vf4.y);
                unsigned b2 = __float_as_uint(vf4.z), b3 = __float_as_uint(vf4.w);
                mma8(o[0][nt], pf[0][0], b0, b1);
                mma8(o[0][nt], pf[0][1], b2, b3);
                mma8(o[1][nt], pf[1][0], b0, b1);
                mma8(o[1][nt], pf[1][1], b2, b3);
            }
        }
        __syncwarp();
    }

    // ---- epilogue ----
#pragma unroll
    for (int bb = 0; bb < 2; bb++) {
        float inv0 = 1.0f / l_[bb][0], inv1 = 1.0f / l_[bb][1];
        float* Cb = Ctx + ((size_t)b * S_LEN + qb + w32 + bb * 16) * D_MODEL
                        + h * HEAD_DIM;
#pragma unroll
        for (int nt = 0; nt < 8; nt++) {
            *(float2*)&Cb[(size_t)g * D_MODEL + nt * 8 + 2 * tig] =
                make_float2(f2tff(o[bb][nt][0] * inv0), f2tff(o[bb][nt][1] * inv0));
            *(float2*)&Cb[(size_t)(g + 8) * D_MODEL + nt * 8 + 2 * tig] =
                make_float2(f2tff(o[bb][nt][2] * inv1), f2tff(o[bb][nt][3] * inv1));
        }
    }
}

// =================================================================
// Launch
// =================================================================
extern "C" void kernel_launch(void* const* d_in, const int* in_sizes, int n_in,
                              void* d_out, int out_size)
{
    const float* x  = (const float*)d_in[0];
    const float* Wq = (const float*)d_in[1];
    const float* Wk = (const float*)d_in[2];
    const float* Wv = (const float*)d_in[3];
    const float* Wo = (const float*)d_in[4];
    float* out = (float*)d_out;

    float *Qf, *Kf, *Vf, *C;
    cudaGetSymbolAddress((void**)&Qf, g_Qf);
    cudaGetSymbolAddress((void**)&Kf, g_Kf);
    cudaGetSymbolAddress((void**)&Vf, g_Vf);
    cudaGetSymbolAddress((void**)&C, g_C);

    // 0: rope table
    rope_table_kernel<<<(S_LEN * 32 + 255) / 256, 256>>>();

    // 1: pre-round + permute x and weights into fragment order
    int nthreads = NTOK * (D_MODEL / 4) + 4 * D_MODEL * (D_MODEL / 4);
    preround_permute_kernel<<<(nthreads + 255) / 256, 256>>>(x, Wq, Wk, Wv, Wo);

    // 2: fused QKV projections; Q/K/V all written in attention frag order
    cudaFuncSetAttribute(qkv_gemm_kernel, cudaFuncAttributeMaxDynamicSharedMemorySize, QKV_SMEM);
    qkv_gemm_kernel<<<dim3(D_MODEL / 128, NTOK / 128, 3), 128, QKV_SMEM>>>();

    // 3: attention (all-frag inputs)
    cudaFuncSetAttribute(attn_tf32, cudaFuncAttributeMaxDynamicSharedMemorySize, ATT_SMEM5);
    attn_tf32<<<dim3(S_LEN / 128, N_HEADS, BATCH), 128, ATT_SMEM5>>>(Qf, Kf, Vf, C);

    // 4: output projection
    out_gemm_kernel<<<dim3(D_MODEL / 128, NTOK / 128), 128>>>(out);
}

// round 14
// speedup vs baseline: 1.3067x; 1.3056x over previous
#include <cuda_runtime.h>
#include <cuda_fp16.h>
#include <math.h>
#include <stdint.h>

#define S_LEN    2048
#define D_MODEL  1024
#define N_HEADS  16
#define HEAD_DIM 64
#define BATCH    2
#define NTOK     (BATCH * S_LEN)   // 4096

// -------- scratch (device globals: no allocations allowed) --------
__device__ __half g_Qh[NTOK * D_MODEL];           // Q, attention A-frag order, fp16
__device__ __half g_Kh[NTOK * D_MODEL];           // K, attention B-frag order, fp16
__device__ __half g_Vh[NTOK * D_MODEL];           // V, attention B-frag order, fp16
__device__ float  g_C[NTOK * D_MODEL];
__device__ float  g_Xp[NTOK * D_MODEL];           // x, tf32-rounded, A-frag order
__device__ float  g_Wp[4][D_MODEL * D_MODEL];     // weights, tf32-rounded, B-frag order
__device__ float  g_cos[S_LEN * 32];
__device__ float  g_sin[S_LEN * 32];

#define LOG2E 1.4426950408889634f

__device__ __forceinline__ unsigned f2tf(float x) {
    unsigned u;
    asm("cvt.rna.tf32.f32 %0, %1;" : "=r"(u) : "f"(x));
    return u;
}
__device__ __forceinline__ float f2tff(float x) { return __uint_as_float(f2tf(x)); }

// pack (lo, hi) floats into f16x2 register
__device__ __forceinline__ unsigned h2u(float lo, float hi) {
    unsigned u;
    asm("cvt.rn.f16x2.f32 %0, %1, %2;" : "=r"(u) : "f"(hi), "f"(lo));
    return u;
}

__device__ __forceinline__ void mma8(float c[4], const unsigned a[4],
                                     unsigned b0, unsigned b1) {
    asm volatile(
        "mma.sync.aligned.m16n8k8.row.col.f32.tf32.tf32.f32 "
        "{%0,%1,%2,%3},{%4,%5,%6,%7},{%8,%9},{%0,%1,%2,%3};"
        : "+f"(c[0]), "+f"(c[1]), "+f"(c[2]), "+f"(c[3])
        : "r"(a[0]), "r"(a[1]), "r"(a[2]), "r"(a[3]), "r"(b0), "r"(b1));
}

__device__ __forceinline__ void mma16(float c[4], const unsigned a[4],
                                      unsigned b0, unsigned b1) {
    asm volatile(
        "mma.sync.aligned.m16n8k16.row.col.f32.f16.f16.f32 "
        "{%0,%1,%2,%3},{%4,%5,%6,%7},{%8,%9},{%0,%1,%2,%3};"
        : "+f"(c[0]), "+f"(c[1]), "+f"(c[2]), "+f"(c[3])
        : "r"(a[0]), "r"(a[1]), "r"(a[2]), "r"(a[3]), "r"(b0), "r"(b1));
}

// =================================================================
// Preround + permute x (A-frag) and weights (B-frag)  [R11 passing]
// =================================================================
__global__ void preround_permute_kernel(const float* __restrict__ x,
                                        const float* __restrict__ Wq,
                                        const float* __restrict__ Wk,
                                        const float* __restrict__ Wv,
                                        const float* __restrict__ Wo)
{
    const int NXq = NTOK * (D_MODEL / 4);
    const int NWq = D_MODEL * (D_MODEL / 4);
    int idx = blockIdx.x * blockDim.x + threadIdx.x;
    if (idx < NXq) {
        int m = idx >> 8, k4 = idx & 255;
        float4 v = *(const float4*)&x[(size_t)m * D_MODEL + k4 * 4];
        int m_tile = m >> 7, mrow = m & 127;
        int mt = mrow >> 4, r8 = (mrow >> 3) & 1, g = mrow & 7;
        int stage = k4 >> 2, ks = (k4 >> 1) & 1, e4 = k4 & 1;
        int j = r8 + 2 * e4;
        float* base = g_Xp + ((((size_t)m_tile * 64 + stage) * 2 + ks) * 8 + mt) * 128;
        base[(g * 4 + 0) * 4 + j] = f2tff(v.x);
        base[(g * 4 + 1) * 4 + j] = f2tff(v.y);
        base[(g * 4 + 2) * 4 + j] = f2tff(v.z);
        base[(g * 4 + 3) * 4 + j] = f2tff(v.w);
    } else if (idx < NXq + 4 * NWq) {
        int r = idx - NXq;
        int w = r / NWq; r -= w * NWq;
        int n = r >> 8, k4 = r & 255;
        const float* ws[4] = {Wq, Wk, Wv, Wo};
        float4 v = *(const float4*)&ws[w][(size_t)n * D_MODEL + k4 * 4];
        int n_tile = n >> 7, nrow = n & 127;
        int nt = nrow >> 3, g = nrow & 7;
        int stage = k4 >> 2, ks = (k4 >> 1) & 1, j = k4 & 1;
        float* base = g_Wp[w] + ((((size_t)n_tile * 64 + stage) * 2 + ks) * 16 + nt) * 64;
        base[(g * 4 + 0) * 2 + j] = f2tff(v.x);
        base[(g * 4 + 1) * 2 + j] = f2tff(v.y);
        base[(g * 4 + 2) * 2 + j] = f2tff(v.z);
        base[(g * 4 + 3) * 2 + j] = f2tff(v.w);
    }
}

// =================================================================
// RoPE table
// =================================================================
__global__ void rope_table_kernel()
{
    int i = blockIdx.x * blockDim.x + threadIdx.x;
    if (i >= S_LEN * 32) return;
    int pos = i >> 5;
    int f   = i & 31;
    float e    = (float)(2 * f) / 64.0f;
    float pw   = powf(10000.0f, e);
    float invf = 1.0f / pw;
    float angf = (float)pos * invf;
    double s, c;
    sincos((double)angf, &s, &c);
    g_cos[i] = (float)c;
    g_sin[i] = (float)s;
}

// =================================================================
// QKV GEMM: tf32 frag-order mainloop (R11-exact). Epilogue converts
// to fp16 and writes Q/K/V DIRECTLY in attention fragment order via
// register packing — coalesced, no scatter, no staging.
// =================================================================
__global__ __launch_bounds__(128, 2) void qkv_gemm_kernel()
{
    __shared__ __align__(16) float As[3][2048];
    __shared__ __align__(16) float Bs[3][2048];

    const int z = blockIdx.z;
    const int t = threadIdx.x, warp = t >> 5, lane = t & 31;
    const int g = lane >> 2, tig = lane & 3;
    const int mtb = (warp >> 1) * 4;       // A-frag mt base
    const int ntb = (warp & 1) * 8;        // B-frag nt base
    const int wm = (warp >> 1) * 64;
    const int wn = (warp & 1) * 64;
    const int mb = blockIdx.y * 128, nb = blockIdx.x * 128;

    const float* Ag = g_Xp + (size_t)blockIdx.y * 64 * 2048;
    const float* Bg = g_Wp[z] + (size_t)blockIdx.x * 64 * 2048;

    const int rope_mode = (z < 2) ? 1 : 0;
    const float scale = (z == 0) ? 0.125f * LOG2E : 1.0f;

    float acc[4][8][4];
#pragma unroll
    for (int mt = 0; mt < 4; mt++)
#pragma unroll
        for (int nt = 0; nt < 8; nt++)
#pragma unroll
            for (int i = 0; i < 4; i++) acc[mt][nt][i] = 0.f;

#define LOADP(buf, s)                                                              \
    do {                                                                           \
        _Pragma("unroll")                                                          \
        for (int ii = 0; ii < 4; ii++) {                                           \
            int q = t + ii * 128;                                                  \
            unsigned da = (unsigned)__cvta_generic_to_shared(&As[buf][q * 4]);     \
            asm volatile("cp.async.cg.shared.global [%0], [%1], 16;"               \
                         :: "r"(da), "l"(Ag + (size_t)(s) * 2048 + q * 4));        \
            unsigned db = (unsigned)__cvta_generic_to_shared(&Bs[buf][q * 4]);     \
            asm volatile("cp.async.cg.shared.global [%0], [%1], 16;"               \
                         :: "r"(db), "l"(Bg + (size_t)(s) * 2048 + q * 4));        \
        }                                                                          \
        asm volatile("cp.async.commit_group;");                                    \
    } while (0)

    LOADP(0, 0);
    LOADP(1, 1);

    for (int i = 0; i < 64; i++) {
        asm volatile("cp.async.wait_group 1;");
        __syncthreads();
        if (i + 2 < 64) LOADP((i + 2) % 3, i + 2);
        const float* Ab = As[i % 3];
        const float* Bb = Bs[i % 3];

#pragma unroll
        for (int ks = 0; ks < 2; ks++) {
            unsigned af[4][4], bf[8][2];
#pragma unroll
            for (int mt = 0; mt < 4; mt++) {
                float4 a4 = *(const float4*)&Ab[((ks * 8 + mtb + mt) * 32 + lane) * 4];
                af[mt][0] = __float_as_uint(a4.x);
                af[mt][1] = __float_as_uint(a4.y);
                af[mt][2] = __float_as_uint(a4.z);
                af[mt][3] = __float_as_uint(a4.w);
            }
#pragma unroll
            for (int nt = 0; nt < 8; nt++) {
                float2 b2 = *(const float2*)&Bs[i % 3][((ks * 16 + ntb + nt) * 32 + lane) * 2];
                bf[nt][0] = __float_as_uint(b2.x);
                bf[nt][1] = __float_as_uint(b2.y);
            }
#pragma unroll
            for (int mt = 0; mt < 4; mt++)
#pragma unroll
                for (int nt = 0; nt < 8; nt++)
                    mma8(acc[mt][nt], af[mt], bf[nt][0], bf[nt][1]);
        }
        (void)Bb;
    }

    // ---- epilogue: RoPE (fp32) then fp16 frag-order outputs ----
    const int bI   = mb >> 11;
    const int qt   = (mb & 2047) >> 7;
    const int tile = ((mb & 2047) + wm) >> 6;
    const int head = (nb + wn) >> 6;
    const int bh   = bI * N_HEADS + head;

#pragma unroll
    for (int mt = 0; mt < 4; mt++) {
        float rv[8][4];
#pragma unroll
        for (int nt = 0; nt < 8; nt++) {
            float v0 = acc[mt][nt][0], v1 = acc[mt][nt][1];
            float v2 = acc[mt][nt][2], v3 = acc[mt][nt][3];
            if (rope_mode) {
                int row = mb + wm + mt * 16 + g;
                int col = nb + wn + nt * 8 + 2 * tig;
                int fi = (col & 63) >> 1;
                int p0 = row & (S_LEN - 1);
                int p1 = (row + 8) & (S_LEN - 1);
                float c0 = g_cos[p0 * 32 + fi], s0 = g_sin[p0 * 32 + fi];
                float c1 = g_cos[p1 * 32 + fi], s1 = g_sin[p1 * 32 + fi];
                float r0 = v0 * c0 - v1 * s0, r1 = v0 * s0 + v1 * c0;
                float r2 = v2 * c1 - v3 * s1, r3 = v2 * s1 + v3 * c1;
                v0 = r0 * scale; v1 = r1 * scale;
                v2 = r2 * scale; v3 = r3 * scale;
            }
            rv[nt][0] = v0; rv[nt][1] = v1; rv[nt][2] = v2; rv[nt][3] = v3;
        }

        if (z == 0) {
            // Q A-frags: uint4 per (kc=j): {a0,a1,a2,a3}
            int wa = 2 * (warp >> 1) + (mt >> 1), bb = mt & 1;
            __half* base = g_Qh + ((size_t)bh * 16 + qt) * 8192
                         + (size_t)((wa * 2 + bb) * 4) * 256;
#pragma unroll
            for (int j = 0; j < 4; j++) {
                uint4 u;
                u.x = h2u(rv[2 * j][0],     rv[2 * j][1]);
                u.y = h2u(rv[2 * j][2],     rv[2 * j][3]);
                u.z = h2u(rv[2 * j + 1][0], rv[2 * j + 1][1]);
                u.w = h2u(rv[2 * j + 1][2], rv[2 * j + 1][3]);
                *(uint4*)(base + (size_t)(j * 32 + lane) * 8) = u;
            }
        } else if (z == 1) {
            // K B-frags: uint2 {b0,b1} per (kc=j, nt_k)
            __half* base = g_Kh + ((size_t)bh * 32 + tile) * 4096;
#pragma unroll
            for (int j = 0; j < 4; j++) {
                uint2 lo, hi;
                lo.x = h2u(rv[2 * j][0],     rv[2 * j][1]);
                lo.y = h2u(rv[2 * j + 1][0], rv[2 * j + 1][1]);
                hi.x = h2u(rv[2 * j][2],     rv[2 * j][3]);
                hi.y = h2u(rv[2 * j + 1][2], rv[2 * j + 1][3]);
                *(uint2*)(base + (size_t)((j * 8 + 2 * mt) * 32 + lane) * 4) = lo;
                *(uint2*)(base + (size_t)((j * 8 + 2 * mt + 1) * 32 + lane) * 4) = hi;
            }
        } else {
            // V B-frags: token-adjacent pairs via shfl.xor(4); kcp = mt
            __half* base = g_Vh + ((size_t)bh * 32 + tile) * 4096;
            const int tk = g >> 1, b1off = (g & 1) * 2;
#pragma unroll
            for (int nt = 0; nt < 8; nt++) {
                float u0 = __shfl_xor_sync(0xffffffffu, rv[nt][0], 4);
                float u1 = __shfl_xor_sync(0xffffffffu, rv[nt][1], 4);
                float u2 = __shfl_xor_sync(0xffffffffu, rv[nt][2], 4);
                float u3 = __shfl_xor_sync(0xffffffffu, rv[nt][3], 4);
                unsigned w0, w1;
                if ((g & 1) == 0) {
                    w0 = h2u(rv[nt][0], u0);   // b0, dim c
                    w1 = h2u(rv[nt][1], u1);   // b0, dim c+1
                } else {
                    w0 = h2u(u2, rv[nt][2]);   // b1, dim c
                    w1 = h2u(u3, rv[nt][3]);   // b1, dim c+1
                }
                unsigned o0 = (unsigned)((mt * 8 + nt) * 32 + 8 * tig + tk) * 4 + b1off;
                unsigned o1 = (unsigned)((mt * 8 + nt) * 32 + 8 * tig + 4 + tk) * 4 + b1off;
                *(unsigned*)(base + o0) = w0;
                *(unsigned*)(base + o1) = w1;
            }
        }
    }
}

// =================================================================
// Output GEMM: A = g_C row-major fp32, B = Wo frag-order. [R11 passing]
// =================================================================
#define AST 20

__global__ __launch_bounds__(128, 2) void out_gemm_kernel(float* __restrict__ out)
{
    __shared__ __align__(16) float As[3][128 * AST];
    __shared__ __align__(16) float Bs[3][2048];

    const int t = threadIdx.x, warp = t >> 5, lane = t & 31;
    const int g = lane >> 2, tig = lane & 3;
    const int wm = (warp >> 1) * 64;
    const int ntb = (warp & 1) * 8;
    const int mb = blockIdx.y * 128, nb = blockIdx.x * 128;

    const float* A = g_C;
    const float* Bg = g_Wp[3] + (size_t)blockIdx.x * 64 * 2048;

    float acc[4][8][4];
#pragma unroll
    for (int mt = 0; mt < 4; mt++)
#pragma unroll
        for (int nt = 0; nt < 8; nt++)
#pragma unroll
            for (int i = 0; i < 4; i++) acc[mt][nt][i] = 0.f;

    const int lrow = t >> 2, lcol = (t & 3) * 4;

#define LOADO(buf, s)                                                              \
    do {                                                                           \
        _Pragma("unroll")                                                          \
        for (int rr = 0; rr < 4; rr++) {                                           \
            int row = lrow + rr * 32;                                              \
            unsigned da = (unsigned)__cvta_generic_to_shared(                      \
                &As[buf][row * AST + lcol]);                                       \
            asm volatile("cp.async.cg.shared.global [%0], [%1], 16;"               \
                :: "r"(da), "l"(A + (size_t)(mb + row) * D_MODEL + (s) * 16 + lcol)); \
            int q = t + rr * 128;                                                  \
            unsigned db = (unsigned)__cvta_generic_to_shared(&Bs[buf][q * 4]);     \
            asm volatile("cp.async.cg.shared.global [%0], [%1], 16;"               \
                :: "r"(db), "l"(Bg + (size_t)(s) * 2048 + q * 4));                 \
        }                                                                          \
        asm volatile("cp.async.commit_group;");                                    \
    } while (0)

    LOADO(0, 0);
    LOADO(1, 1);

    for (int i = 0; i < 64; i++) {
        asm volatile("cp.async.wait_group 1;");
        __syncthreads();
        if (i + 2 < 64) LOADO((i + 2) % 3, i + 2);
        const float* Ab = As[i % 3];
        const float* Bb = Bs[i % 3];

#pragma unroll
        for (int ks = 0; ks < 2; ks++) {
            const int kb = ks * 8;
            unsigned af[4][4], bf[8][2];
#pragma unroll
            for (int mt = 0; mt < 4; mt++) {
                int r0 = wm + mt * 16 + g;
                af[mt][0] = __float_as_uint(Ab[r0 * AST + kb + tig]);
                af[mt][1] = __float_as_uint(Ab[(r0 + 8) * AST + kb + tig]);
                af[mt][2] = __float_as_uint(Ab[r0 * AST + kb + tig + 4]);
                af[mt][3] = __float_as_uint(Ab[(r0 + 8) * AST + kb + tig + 4]);
            }
#pragma unroll
            for (int nt = 0; nt < 8; nt++) {
                float2 b2 = *(const float2*)&Bb[((ks * 16 + ntb + nt) * 32 + lane) * 2];
                bf[nt][0] = __float_as_uint(b2.x);
                bf[nt][1] = __float_as_uint(b2.y);
            }
#pragma unroll
            for (int mt = 0; mt < 4; mt++)
#pragma unroll
                for (int nt = 0; nt < 8; nt++)
                    mma8(acc[mt][nt], af[mt], bf[nt][0], bf[nt][1]);
        }
    }

#pragma unroll
    for (int mt = 0; mt < 4; mt++) {
#pragma unroll
        for (int nt = 0; nt < 8; nt++) {
            int row = mb + wm + mt * 16 + g;
            int col = nb + (warp & 1) * 64 + nt * 8 + 2 * tig;
            *(float2*)&out[(size_t)row * D_MODEL + col] =
                make_float2(acc[mt][nt][0], acc[mt][nt][1]);
            *(float2*)&out[(size_t)(row + 8) * D_MODEL + col] =
                make_float2(acc[mt][nt][2], acc[mt][nt][3]);
        }
    }
}

// =================================================================
// FP16 flash attention, causal. 128 threads = 4 warps, 32 q-rows/warp.
// Q/K/V in global fragment order (fp16). P A-frags are register-local
// (no P smem). smem = 16 KB static (K,V frag tiles).
// =================================================================
__global__ __launch_bounds__(128, 2) void attn_f16(
    const __half* __restrict__ Qf, const __half* __restrict__ Kf,
    const __half* __restrict__ Vf, float* __restrict__ Ctx)
{
    __shared__ __align__(16) __half Ksf[4096];
    __shared__ __align__(16) __half Vsf[4096];

    const int t = threadIdx.x, warp = t >> 5, lane = t & 31;
    const int g = lane >> 2, tig = lane & 3;
    const int qb = ((int)gridDim.x - 1 - (int)blockIdx.x) * 128;  // heavy tiles first
    const int h  = blockIdx.y, b = blockIdx.z;
    const int w32 = warp * 32;
    const int bh = b * N_HEADS + h;

    // ---- Q A-fragments: direct coalesced uint4 loads ----
    const __half* Qblk = Qf + ((size_t)bh * 16 + (qb >> 7)) * 8192;
    unsigned qf[2][4][4];
#pragma unroll
    for (int bb = 0; bb < 2; bb++)
#pragma unroll
        for (int kc = 0; kc < 4; kc++) {
            uint4 u = *(const uint4*)(Qblk + (size_t)(((warp * 2 + bb) * 4 + kc) * 32 + lane) * 8);
            qf[bb][kc][0] = u.x; qf[bb][kc][1] = u.y;
            qf[bb][kc][2] = u.z; qf[bb][kc][3] = u.w;
        }

    float m_[2][2], l_[2][2];
    float o[2][8][4];
#pragma unroll
    for (int bb = 0; bb < 2; bb++) {
        m_[bb][0] = -1e30f; m_[bb][1] = -1e30f;
        l_[bb][0] = 0.f;    l_[bb][1] = 0.f;
#pragma unroll
        for (int nt = 0; nt < 8; nt++)
#pragma unroll
            for (int i = 0; i < 4; i++) o[bb][nt][i] = 0.f;
    }

    const int wrow_max = qb + w32 + 31;

    for (int kt = 0; kt <= qb + 64; kt += 64) {
        __syncthreads();   // prev-iter Ksf/Vsf reads complete
        const uint4* Kg = (const uint4*)(Kf + ((size_t)bh * 32 + (kt >> 6)) * 4096);
        const uint4* Vg = (const uint4*)(Vf + ((size_t)bh * 32 + (kt >> 6)) * 4096);
#pragma unroll
        for (int i = 0; i < 4; i++) {
            ((uint4*)Ksf)[t + i * 128] = Kg[t + i * 128];
            ((uint4*)Vsf)[t + i * 128] = Vg[t + i * 128];
        }
        __syncthreads();

        if (kt > wrow_max) continue;

        // ---- S = Q K^T (m16n8k16) ----
        float s[2][8][4];
#pragma unroll
        for (int nt = 0; nt < 8; nt++) {
            float c0[4] = {0.f, 0.f, 0.f, 0.f};
            float c1[4] = {0.f, 0.f, 0.f, 0.f};
#pragma unroll
            for (int kc = 0; kc < 4; kc++) {
                uint2 kb = *(const uint2*)(Ksf + (size_t)((kc * 8 + nt) * 32 + lane) * 4);
                mma16(c0, qf[0][kc], kb.x, kb.y);
                mma16(c1, qf[1][kc], kb.x, kb.y);
            }
#pragma unroll
            for (int i = 0; i < 4; i++) { s[0][nt][i] = c0[i]; s[1][nt][i] = c1[i]; }
        }

        // ---- causal mask + online softmax (log2 domain) ----
#pragma unroll
        for (int bb = 0; bb < 2; bb++) {
            const int r0 = qb + w32 + bb * 16 + g;
            const int r1 = r0 + 8;
            if (kt + 63 > qb + w32 + bb * 16) {
#pragma unroll
                for (int nt = 0; nt < 8; nt++) {
                    int k0 = kt + nt * 8 + 2 * tig;
                    if (k0 > r0)     s[bb][nt][0] = -1e30f;
                    if (k0 + 1 > r0) s[bb][nt][1] = -1e30f;
                    if (k0 > r1)     s[bb][nt][2] = -1e30f;
                    if (k0 + 1 > r1) s[bb][nt][3] = -1e30f;
                }
            }

            float mx0 = -1e30f, mx1 = -1e30f;
#pragma unroll
            for (int nt = 0; nt < 8; nt++) {
                mx0 = fmaxf(mx0, fmaxf(s[bb][nt][0], s[bb][nt][1]));
                mx1 = fmaxf(mx1, fmaxf(s[bb][nt][2], s[bb][nt][3]));
            }
            mx0 = fmaxf(mx0, __shfl_xor_sync(0xffffffffu, mx0, 1));
            mx0 = fmaxf(mx0, __shfl_xor_sync(0xffffffffu, mx0, 2));
            mx1 = fmaxf(mx1, __shfl_xor_sync(0xffffffffu, mx1, 1));
            mx1 = fmaxf(mx1, __shfl_xor_sync(0xffffffffu, mx1, 2));

            float nm0 = fmaxf(m_[bb][0], mx0), nm1 = fmaxf(m_[bb][1], mx1);
            float a0 = exp2f(m_[bb][0] - nm0), a1 = exp2f(m_[bb][1] - nm1);
            float sum0 = 0.f, sum1 = 0.f;
#pragma unroll
            for (int nt = 0; nt < 8; nt++) {
                s[bb][nt][0] = exp2f(s[bb][nt][0] - nm0);
                s[bb][nt][1] = exp2f(s[bb][nt][1] - nm0);
                s[bb][nt][2] = exp2f(s[bb][nt][2] - nm1);
                s[bb][nt][3] = exp2f(s[bb][nt][3] - nm1);
                sum0 += s[bb][nt][0] + s[bb][nt][1];
                sum1 += s[bb][nt][2] + s[bb][nt][3];
            }
            sum0 += __shfl_xor_sync(0xffffffffu, sum0, 1);
            sum0 += __shfl_xor_sync(0xffffffffu, sum0, 2);
            sum1 += __shfl_xor_sync(0xffffffffu, sum1, 1);
            sum1 += __shfl_xor_sync(0xffffffffu, sum1, 2);

            l_[bb][0] = l_[bb][0] * a0 + sum0;
            l_[bb][1] = l_[bb][1] * a1 + sum1;
            m_[bb][0] = nm0; m_[bb][1] = nm1;
#pragma unroll
            for (int nt = 0; nt < 8; nt++) {
                o[bb][nt][0] *= a0; o[bb][nt][1] *= a0;
                o[bb][nt][2] *= a1; o[bb][nt][3] *= a1;
            }
        }

        // ---- O += P @ V ; P A-frags packed from registers ----
#pragma unroll
        for (int kcp = 0; kcp < 4; kcp++) {
            unsigned pa[2][4];
#pragma unroll
            for (int bb = 0; bb < 2; bb++) {
                pa[bb][0] = h2u(s[bb][2 * kcp][0],     s[bb][2 * kcp][1]);
                pa[bb][1] = h2u(s[bb][2 * kcp][2],     s[bb][2 * kcp][3]);
                pa[bb][2] = h2u(s[bb][2 * kcp + 1][0], s[bb][2 * kcp + 1][1]);
                pa[bb][3] = h2u(s[bb][2 * kcp + 1][2], s[bb][2 * kcp + 1][3]);
            }
#pragma unroll
            for (int nt = 0; nt < 8; nt++) {
                uint2 vb = *(const uint2*)(Vsf + (size_t)((kcp * 8 + nt) * 32 + lane) * 4);
                mma16(o[0][nt], pa[0], vb.x, vb.y);
                mma16(o[1][nt], pa[1], vb.x, vb.y);
            }
        }
    }

    // ---- epilogue: normalize, round to tf32 (out-GEMM input), store ----
#pragma unroll
    for (int bb = 0; bb < 2; bb++) {
        float inv0 = 1.0f / l_[bb][0], inv1 = 1.0f / l_[bb][1];
        float* Cb = Ctx + ((size_t)b * S_LEN + qb + w32 + bb * 16) * D_MODEL
                        + h * HEAD_DIM;
#pragma unroll
        for (int nt = 0; nt < 8; nt++) {
            *(float2*)&Cb[(size_t)g * D_MODEL + nt * 8 + 2 * tig] =
                make_float2(f2tff(o[bb][nt][0] * inv0), f2tff(o[bb][nt][1] * inv0));
            *(float2*)&Cb[(size_t)(g + 8) * D_MODEL + nt * 8 + 2 * tig] =
                make_float2(f2tff(o[bb][nt][2] * inv1), f2tff(o[bb][nt][3] * inv1));
        }
    }
}

// =================================================================
// Launch
// =================================================================
extern "C" void kernel_launch(void* const* d_in, const int* in_sizes, int n_in,
                              void* d_out, int out_size)
{
    const float* x  = (const float*)d_in[0];
    const float* Wq = (const float*)d_in[1];
    const float* Wk = (const float*)d_in[2];
    const float* Wv = (const float*)d_in[3];
    const float* Wo = (const float*)d_in[4];
    float* out = (float*)d_out;

    __half *Qh, *Kh, *Vh;
    float *C;
    cudaGetSymbolAddress((void**)&Qh, g_Qh);
    cudaGetSymbolAddress((void**)&Kh, g_Kh);
    cudaGetSymbolAddress((void**)&Vh, g_Vh);
    cudaGetSymbolAddress((void**)&C, g_C);

    // 0: rope table
    rope_table_kernel<<<(S_LEN * 32 + 255) / 256, 256>>>();

    // 1: pre-round + permute x and weights (tf32 GEMM operands)
    int nthreads = NTOK * (D_MODEL / 4) + 4 * D_MODEL * (D_MODEL / 4);
    preround_permute_kernel<<<(nthreads + 255) / 256, 256>>>(x, Wq, Wk, Wv, Wo);

    // 2: QKV projections; fp16 frag-order outputs via register packing
    qkv_gemm_kernel<<<dim3(D_MODEL / 128, NTOK / 128, 3), 128>>>();

    // 3: fp16 attention
    attn_f16<<<dim3(S_LEN / 128, N_HEADS, BATCH), 128>>>(Qh, Kh, Vh, C);

    // 4: output projection (tf32)
    out_gemm_kernel<<<dim3(D_MODEL / 128, NTOK / 128), 128>>>(out);
}

// round 15
// speedup vs baseline: 1.8717x; 1.4324x over previous
#include <cuda_runtime.h>
#include <cuda_fp16.h>
#include <math.h>
#include <stdint.h>

#define S_LEN    2048
#define D_MODEL  1024
#define N_HEADS  16
#define HEAD_DIM 64
#define BATCH    2
#define NTOK     (BATCH * S_LEN)   // 4096

// -------- scratch (device globals: no allocations allowed) --------
__device__ __half g_Qh[NTOK * D_MODEL];           // Q, attention A-frag order
__device__ __half g_Kh[NTOK * D_MODEL];           // K, attention B-frag order
__device__ __half g_Vh[NTOK * D_MODEL];           // V, attention B-frag order
__device__ __half g_Ch[NTOK * D_MODEL];           // ctx, out-GEMM A-frag order
__device__ __half g_Xh[NTOK * D_MODEL];           // x, GEMM A-frag order
__device__ __half g_Wh[4][D_MODEL * D_MODEL];     // weights, GEMM B-frag order
__device__ float  g_cos[S_LEN * 32];
__device__ float  g_sin[S_LEN * 32];

#define LOG2E 1.4426950408889634f

__device__ __forceinline__ unsigned h2u(float lo, float hi) {
    unsigned u;
    asm("cvt.rn.f16x2.f32 %0, %1, %2;" : "=r"(u) : "f"(hi), "f"(lo));
    return u;
}

__device__ __forceinline__ void mma16(float c[4], const unsigned a[4],
                                      unsigned b0, unsigned b1) {
    asm volatile(
        "mma.sync.aligned.m16n8k16.row.col.f32.f16.f16.f32 "
        "{%0,%1,%2,%3},{%4,%5,%6,%7},{%8,%9},{%0,%1,%2,%3};"
        : "+f"(c[0]), "+f"(c[1]), "+f"(c[2]), "+f"(c[3])
        : "r"(a[0]), "r"(a[1]), "r"(a[2]), "r"(a[3]), "r"(b0), "r"(b1));
}

// =================================================================
// Preround + permute to fp16 fragment layouts.
// A-frag (x): [m_tile(32)][kchunk(64)][mt(8)][lane(32)] uint4 (8 halves)
//   halves: a0={row g,k0,k0+1} a1={g+8,same} a2={g,k0+8,k0+9} a3={g+8,same},
//   k0 = kchunk*16 + 2*tig.
// B-frag (W): [n_tile(8)][kchunk(64)][nt(16)][lane(32)] uint2 (4 halves)
//   halves: b0={n,k0,k0+1} b1={n,k0+8,k0+9}, n = nt*8+g.
// =================================================================
__global__ void preround_permute_kernel(const float* __restrict__ x,
                                        const float* __restrict__ Wq,
                                        const float* __restrict__ Wk,
                                        const float* __restrict__ Wv,
                                        const float* __restrict__ Wo)
{
    const int NXq = NTOK * (D_MODEL / 4);
    const int NWq = D_MODEL * (D_MODEL / 4);
    int idx = blockIdx.x * blockDim.x + threadIdx.x;
    if (idx < NXq) {
        int m = idx >> 8, k4 = idx & 255;
        float4 v = *(const float4*)&x[(size_t)m * D_MODEL + k4 * 4];
        int m_tile = m >> 7, mrow = m & 127;
        int mt = mrow >> 4, rr = mrow & 15, g = rr & 7, rh = rr >> 3;
        int kchunk = k4 >> 2, kk0 = (k4 & 3) * 4;       // 0,4,8,12
        int tig0 = (kk0 & 7) >> 1;                      // 0 or 2
        int id0 = (kk0 < 8 ? 0 : 4) + rh * 2;
        __half* base = g_Xh + ((size_t)(m_tile * 64 + kchunk) * 8 + mt) * 256;
        *(unsigned*)(base + (size_t)(g * 4 + tig0) * 8 + id0)     = h2u(v.x, v.y);
        *(unsigned*)(base + (size_t)(g * 4 + tig0 + 1) * 8 + id0) = h2u(v.z, v.w);
    } else if (idx < NXq + 4 * NWq) {
        int r = idx - NXq;
        int w = r / NWq; r -= w * NWq;
        int n = r >> 8, k4 = r & 255;
        const float* ws[4] = {Wq, Wk, Wv, Wo};
        float4 v = *(const float4*)&ws[w][(size_t)n * D_MODEL + k4 * 4];
        int n_tile = n >> 7, nrow = n & 127;
        int nt = nrow >> 3, g = nrow & 7;
        int kchunk = k4 >> 2, kk0 = (k4 & 3) * 4;
        int tig0 = (kk0 & 7) >> 1;
        int id0 = (kk0 < 8) ? 0 : 2;
        __half* base = g_Wh[w] + ((size_t)(n_tile * 64 + kchunk) * 16 + nt) * 128;
        *(unsigned*)(base + (size_t)(g * 4 + tig0) * 4 + id0)     = h2u(v.x, v.y);
        *(unsigned*)(base + (size_t)(g * 4 + tig0 + 1) * 4 + id0) = h2u(v.z, v.w);
    }
}

// =================================================================
// RoPE table
// =================================================================
__global__ void rope_table_kernel()
{
    int i = blockIdx.x * blockDim.x + threadIdx.x;
    if (i >= S_LEN * 32) return;
    int pos = i >> 5;
    int f   = i & 31;
    float e    = (float)(2 * f) / 64.0f;
    float pw   = powf(10000.0f, e);
    float invf = 1.0f / pw;
    float angf = (float)pos * invf;
    double s, c;
    sincos((double)angf, &s, &c);
    g_cos[i] = (float)c;
    g_sin[i] = (float)s;
}

// =================================================================
// Shared fp16 GEMM mainloop (both operands frag-order fp16).
// 128x128 CTA tile, 128 thr = 4 warps (2x2), 64x64 warp tile,
// 64 k16 iters, 3-stage cp.async (4KB+4KB per stage).
// =================================================================
__device__ __forceinline__ void f16_gemm_main(
    const __half* __restrict__ Ag, const __half* __restrict__ Bg,
    float acc[4][8][4], __half* As, __half* Bs,
    int t, int mtb, int ntb, int lane)
{
#define LOADH(buf, s)                                                              \
    do {                                                                           \
        _Pragma("unroll")                                                          \
        for (int ii = 0; ii < 2; ii++) {                                           \
            int q = t + ii * 128;                                                  \
            unsigned da = (unsigned)__cvta_generic_to_shared(                      \
                As + (size_t)(buf) * 2048 + q * 8);                                \
            asm volatile("cp.async.cg.shared.global [%0], [%1], 16;"               \
                         :: "r"(da), "l"(Ag + (size_t)(s) * 2048 + q * 8));        \
            unsigned db = (unsigned)__cvta_generic_to_shared(                      \
                Bs + (size_t)(buf) * 2048 + q * 8);                                \
            asm volatile("cp.async.cg.shared.global [%0], [%1], 16;"               \
                         :: "r"(db), "l"(Bg + (size_t)(s) * 2048 + q * 8));        \
        }                                                                          \
        asm volatile("cp.async.commit_group;");                                    \
    } while (0)

    LOADH(0, 0);
    LOADH(1, 1);

    for (int i = 0; i < 64; i++) {
        asm volatile("cp.async.wait_group 1;");
        __syncthreads();
        if (i + 2 < 64) LOADH((i + 2) % 3, i + 2);
        const __half* Ab = As + (i % 3) * 2048;
        const __half* Bb = Bs + (i % 3) * 2048;

        unsigned af[4][4];
        uint2 bf[8];
#pragma unroll
        for (int mt = 0; mt < 4; mt++) {
            uint4 u = *(const uint4*)(Ab + (size_t)((mtb + mt) * 32 + lane) * 8);
            af[mt][0] = u.x; af[mt][1] = u.y; af[mt][2] = u.z; af[mt][3] = u.w;
        }
#pragma unroll
        for (int nt = 0; nt < 8; nt++)
            bf[nt] = *(const uint2*)(Bb + (size_t)((ntb + nt) * 32 + lane) * 4);
#pragma unroll
        for (int mt = 0; mt < 4; mt++)
#pragma unroll
            for (int nt = 0; nt < 8; nt++)
                mma16(acc[mt][nt], af[mt], bf[nt].x, bf[nt].y);
    }
#undef LOADH
}

// =================================================================
// QKV GEMM (fp16): epilogue packs Q/K/V into attention frag order.
// =================================================================
__global__ __launch_bounds__(128, 2) void qkv_gemm_kernel()
{
    __shared__ __align__(16) __half As[3 * 2048];
    __shared__ __align__(16) __half Bs[3 * 2048];

    const int z = blockIdx.z;
    const int t = threadIdx.x, warp = t >> 5, lane = t & 31;
    const int g = lane >> 2, tig = lane & 3;
    const int mtb = (warp >> 1) * 4;
    const int ntb = (warp & 1) * 8;
    const int wm = (warp >> 1) * 64;
    const int wn = (warp & 1) * 64;
    const int mb = blockIdx.y * 128, nb = blockIdx.x * 128;

    const __half* Ag = g_Xh + (size_t)blockIdx.y * 64 * 2048;
    const __half* Bg = g_Wh[z] + (size_t)blockIdx.x * 64 * 2048;

    const int rope_mode = (z < 2) ? 1 : 0;
    const float scale = (z == 0) ? 0.125f * LOG2E : 1.0f;

    float acc[4][8][4];
#pragma unroll
    for (int mt = 0; mt < 4; mt++)
#pragma unroll
        for (int nt = 0; nt < 8; nt++)
#pragma unroll
            for (int i = 0; i < 4; i++) acc[mt][nt][i] = 0.f;

    f16_gemm_main(Ag, Bg, acc, As, Bs, t, mtb, ntb, lane);

    // ---- epilogue: RoPE (fp32) then fp16 frag-order outputs ----
    const int bI   = mb >> 11;
    const int qt   = (mb & 2047) >> 7;
    const int tile = ((mb & 2047) + wm) >> 6;
    const int head = (nb + wn) >> 6;
    const int bh   = bI * N_HEADS + head;

#pragma unroll
    for (int mt = 0; mt < 4; mt++) {
        float rv[8][4];
#pragma unroll
        for (int nt = 0; nt < 8; nt++) {
            float v0 = acc[mt][nt][0], v1 = acc[mt][nt][1];
            float v2 = acc[mt][nt][2], v3 = acc[mt][nt][3];
            if (rope_mode) {
                int row = mb + wm + mt * 16 + g;
                int col = nb + wn + nt * 8 + 2 * tig;
                int fi = (col & 63) >> 1;
                int p0 = row & (S_LEN - 1);
                int p1 = (row + 8) & (S_LEN - 1);
                float c0 = g_cos[p0 * 32 + fi], s0 = g_sin[p0 * 32 + fi];
                float c1 = g_cos[p1 * 32 + fi], s1 = g_sin[p1 * 32 + fi];
                float r0 = v0 * c0 - v1 * s0, r1 = v0 * s0 + v1 * c0;
                float r2 = v2 * c1 - v3 * s1, r3 = v2 * s1 + v3 * c1;
                v0 = r0 * scale; v1 = r1 * scale;
                v2 = r2 * scale; v3 = r3 * scale;
            }
            rv[nt][0] = v0; rv[nt][1] = v1; rv[nt][2] = v2; rv[nt][3] = v3;
        }

        if (z == 0) {
            int wa = 2 * (warp >> 1) + (mt >> 1), bb = mt & 1;
            __half* base = g_Qh + ((size_t)bh * 16 + qt) * 8192
                         + (size_t)((wa * 2 + bb) * 4) * 256;
#pragma unroll
            for (int j = 0; j < 4; j++) {
                uint4 u;
                u.x = h2u(rv[2 * j][0],     rv[2 * j][1]);
                u.y = h2u(rv[2 * j][2],     rv[2 * j][3]);
                u.z = h2u(rv[2 * j + 1][0], rv[2 * j + 1][1]);
                u.w = h2u(rv[2 * j + 1][2], rv[2 * j + 1][3]);
                *(uint4*)(base + (size_t)(j * 32 + lane) * 8) = u;
            }
        } else if (z == 1) {
            __half* base = g_Kh + ((size_t)bh * 32 + tile) * 4096;
#pragma unroll
            for (int j = 0; j < 4; j++) {
                uint2 lo, hi;
                lo.x = h2u(rv[2 * j][0],     rv[2 * j][1]);
                lo.y = h2u(rv[2 * j + 1][0], rv[2 * j + 1][1]);
                hi.x = h2u(rv[2 * j][2],     rv[2 * j][3]);
                hi.y = h2u(rv[2 * j + 1][2], rv[2 * j + 1][3]);
                *(uint2*)(base + (size_t)((j * 8 + 2 * mt) * 32 + lane) * 4) = lo;
                *(uint2*)(base + (size_t)((j * 8 + 2 * mt + 1) * 32 + lane) * 4) = hi;
            }
        } else {
            __half* base = g_Vh + ((size_t)bh * 32 + tile) * 4096;
            const int tk = g >> 1, b1off = (g & 1) * 2;
#pragma unroll
            for (int nt = 0; nt < 8; nt++) {
                float u0 = __shfl_xor_sync(0xffffffffu, rv[nt][0], 4);
                float u1 = __shfl_xor_sync(0xffffffffu, rv[nt][1], 4);
                float u2 = __shfl_xor_sync(0xffffffffu, rv[nt][2], 4);
                float u3 = __shfl_xor_sync(0xffffffffu, rv[nt][3], 4);
                unsigned w0, w1;
                if ((g & 1) == 0) {
                    w0 = h2u(rv[nt][0], u0);
                    w1 = h2u(rv[nt][1], u1);
                } else {
                    w0 = h2u(u2, rv[nt][2]);
                    w1 = h2u(u3, rv[nt][3]);
                }
                unsigned o0 = (unsigned)((mt * 8 + nt) * 32 + 8 * tig + tk) * 4 + b1off;
                unsigned o1 = (unsigned)((mt * 8 + nt) * 32 + 8 * tig + 4 + tk) * 4 + b1off;
                *(unsigned*)(base + o0) = w0;
                *(unsigned*)(base + o1) = w1;
            }
        }
    }
}

// =================================================================
// Output GEMM (fp16): A = g_Ch (A-frag order), B = Wo (B-frag order).
// Epilogue: plain fp32 row-major store to harness output.
// =================================================================
__global__ __launch_bounds__(128, 2) void out_gemm_kernel(float* __restrict__ out)
{
    __shared__ __align__(16) __half As[3 * 2048];
    __shared__ __align__(16) __half Bs[3 * 2048];

    const int t = threadIdx.x, warp = t >> 5, lane = t & 31;
    const int g = lane >> 2, tig = lane & 3;
    const int mtb = (warp >> 1) * 4;
    const int ntb = (warp & 1) * 8;
    const int wm = (warp >> 1) * 64;
    const int wn = (warp & 1) * 64;
    const int mb = blockIdx.y * 128, nb = blockIdx.x * 128;

    const __half* Ag = g_Ch + (size_t)blockIdx.y * 64 * 2048;
    const __half* Bg = g_Wh[3] + (size_t)blockIdx.x * 64 * 2048;

    float acc[4][8][4];
#pragma unroll
    for (int mt = 0; mt < 4; mt++)
#pragma unroll
        for (int nt = 0; nt < 8; nt++)
#pragma unroll
            for (int i = 0; i < 4; i++) acc[mt][nt][i] = 0.f;

    f16_gemm_main(Ag, Bg, acc, As, Bs, t, mtb, ntb, lane);

#pragma unroll
    for (int mt = 0; mt < 4; mt++) {
#pragma unroll
        for (int nt = 0; nt < 8; nt++) {
            int row = mb + wm + mt * 16 + g;
            int col = nb + wn + nt * 8 + 2 * tig;
            *(float2*)&out[(size_t)row * D_MODEL + col] =
                make_float2(acc[mt][nt][0], acc[mt][nt][1]);
            *(float2*)&out[(size_t)(row + 8) * D_MODEL + col] =
                make_float2(acc[mt][nt][2], acc[mt][nt][3]);
        }
    }
}

// =================================================================
// FP16 flash attention, causal (R14 core, 98us). Epilogue now writes
// context DIRECTLY in out-GEMM A-frag order (fp16, coalesced uint4).
// =================================================================
__global__ __launch_bounds__(128, 2) void attn_f16(
    const __half* __restrict__ Qf, const __half* __restrict__ Kf,
    const __half* __restrict__ Vf, __half* __restrict__ Ch)
{
    __shared__ __align__(16) __half Ksf[4096];
    __shared__ __align__(16) __half Vsf[4096];

    const int t = threadIdx.x, warp = t >> 5, lane = t & 31;
    const int g = lane >> 2, tig = lane & 3;
    const int qb = ((int)gridDim.x - 1 - (int)blockIdx.x) * 128;  // heavy tiles first
    const int h  = blockIdx.y, b = blockIdx.z;
    const int w32 = warp * 32;
    const int bh = b * N_HEADS + h;

    const __half* Qblk = Qf + ((size_t)bh * 16 + (qb >> 7)) * 8192;
    unsigned qf[2][4][4];
#pragma unroll
    for (int bb = 0; bb < 2; bb++)
#pragma unroll
        for (int kc = 0; kc < 4; kc++) {
            uint4 u = *(const uint4*)(Qblk + (size_t)(((warp * 2 + bb) * 4 + kc) * 32 + lane) * 8);
            qf[bb][kc][0] = u.x; qf[bb][kc][1] = u.y;
            qf[bb][kc][2] = u.z; qf[bb][kc][3] = u.w;
        }

    float m_[2][2], l_[2][2];
    float o[2][8][4];
#pragma unroll
    for (int bb = 0; bb < 2; bb++) {
        m_[bb][0] = -1e30f; m_[bb][1] = -1e30f;
        l_[bb][0] = 0.f;    l_[bb][1] = 0.f;
#pragma unroll
        for (int nt = 0; nt < 8; nt++)
#pragma unroll
            for (int i = 0; i < 4; i++) o[bb][nt][i] = 0.f;
    }

    const int wrow_max = qb + w32 + 31;

    for (int kt = 0; kt <= qb + 64; kt += 64) {
        __syncthreads();
        const uint4* Kg = (const uint4*)(Kf + ((size_t)bh * 32 + (kt >> 6)) * 4096);
        const uint4* Vg = (const uint4*)(Vf + ((size_t)bh * 32 + (kt >> 6)) * 4096);
#pragma unroll
        for (int i = 0; i < 4; i++) {
            ((uint4*)Ksf)[t + i * 128] = Kg[t + i * 128];
            ((uint4*)Vsf)[t + i * 128] = Vg[t + i * 128];
        }
        __syncthreads();

        if (kt > wrow_max) continue;

        float s[2][8][4];
#pragma unroll
        for (int nt = 0; nt < 8; nt++) {
            float c0[4] = {0.f, 0.f, 0.f, 0.f};
            float c1[4] = {0.f, 0.f, 0.f, 0.f};
#pragma unroll
            for (int kc = 0; kc < 4; kc++) {
                uint2 kb = *(const uint2*)(Ksf + (size_t)((kc * 8 + nt) * 32 + lane) * 4);
                mma16(c0, qf[0][kc], kb.x, kb.y);
                mma16(c1, qf[1][kc], kb.x, kb.y);
            }
#pragma unroll
            for (int i = 0; i < 4; i++) { s[0][nt][i] = c0[i]; s[1][nt][i] = c1[i]; }
        }

#pragma unroll
        for (int bb = 0; bb < 2; bb++) {
            const int r0 = qb + w32 + bb * 16 + g;
            const int r1 = r0 + 8;
            if (kt + 63 > qb + w32 + bb * 16) {
#pragma unroll
                for (int nt = 0; nt < 8; nt++) {
                    int k0 = kt + nt * 8 + 2 * tig;
                    if (k0 > r0)     s[bb][nt][0] = -1e30f;
                    if (k0 + 1 > r0) s[bb][nt][1] = -1e30f;
                    if (k0 > r1)     s[bb][nt][2] = -1e30f;
                    if (k0 + 1 > r1) s[bb][nt][3] = -1e30f;
                }
            }

            float mx0 = -1e30f, mx1 = -1e30f;
#pragma unroll
            for (int nt = 0; nt < 8; nt++) {
                mx0 = fmaxf(mx0, fmaxf(s[bb][nt][0], s[bb][nt][1]));
                mx1 = fmaxf(mx1, fmaxf(s[bb][nt][2], s[bb][nt][3]));
            }
            mx0 = fmaxf(mx0, __shfl_xor_sync(0xffffffffu, mx0, 1));
            mx0 = fmaxf(mx0, __shfl_xor_sync(0xffffffffu, mx0, 2));
            mx1 = fmaxf(mx1, __shfl_xor_sync(0xffffffffu, mx1, 1));
            mx1 = fmaxf(mx1, __shfl_xor_sync(0xffffffffu, mx1, 2));

            float nm0 = fmaxf(m_[bb][0], mx0), nm1 = fmaxf(m_[bb][1], mx1);
            float a0 = exp2f(m_[bb][0] - nm0), a1 = exp2f(m_[bb][1] - nm1);
            float sum0 = 0.f, sum1 = 0.f;
#pragma unroll
            for (int nt = 0; nt < 8; nt++) {
                s[bb][nt][0] = exp2f(s[bb][nt][0] - nm0);
                s[bb][nt][1] = exp2f(s[bb][nt][1] - nm0);
                s[bb][nt][2] = exp2f(s[bb][nt][2] - nm1);
                s[bb][nt][3] = exp2f(s[bb][nt][3] - nm1);
                sum0 += s[bb][nt][0] + s[bb][nt][1];
                sum1 += s[bb][nt][2] + s[bb][nt][3];
            }
            sum0 += __shfl_xor_sync(0xffffffffu, sum0, 1);
            sum0 += __shfl_xor_sync(0xffffffffu, sum0, 2);
            sum1 += __shfl_xor_sync(0xffffffffu, sum1, 1);
            sum1 += __shfl_xor_sync(0xffffffffu, sum1, 2);

            l_[bb][0] = l_[bb][0] * a0 + sum0;
            l_[bb][1] = l_[bb][1] * a1 + sum1;
            m_[bb][0] = nm0; m_[bb][1] = nm1;
#pragma unroll
            for (int nt = 0; nt < 8; nt++) {
                o[bb][nt][0] *= a0; o[bb][nt][1] *= a0;
                o[bb][nt][2] *= a1; o[bb][nt][3] *= a1;
            }
        }

#pragma unroll
        for (int kcp = 0; kcp < 4; kcp++) {
            unsigned pa[2][4];
#pragma unroll
            for (int bb = 0; bb < 2; bb++) {
                pa[bb][0] = h2u(s[bb][2 * kcp][0],     s[bb][2 * kcp][1]);
                pa[bb][1] = h2u(s[bb][2 * kcp][2],     s[bb][2 * kcp][3]);
                pa[bb][2] = h2u(s[bb][2 * kcp + 1][0], s[bb][2 * kcp + 1][1]);
                pa[bb][3] = h2u(s[bb][2 * kcp + 1][2], s[bb][2 * kcp + 1][3]);
            }
#pragma unroll
            for (int nt = 0; nt < 8; nt++) {
                uint2 vb = *(const uint2*)(Vsf + (size_t)((kcp * 8 + nt) * 32 + lane) * 4);
                mma16(o[0][nt], pa[0], vb.x, vb.y);
                mma16(o[1][nt], pa[1], vb.x, vb.y);
            }
        }
    }

    // ---- epilogue: normalize, pack to out-GEMM A-frag order (fp16) ----
    const int m_tile = (b * S_LEN + qb) >> 7;
#pragma unroll
    for (int bb = 0; bb < 2; bb++) {
        float inv0 = 1.0f / l_[bb][0], inv1 = 1.0f / l_[bb][1];
        const int mt = warp * 2 + bb;
        __half* base = g_Ch + ((size_t)(m_tile * 64 + h * 4) * 8 + mt) * 256
                     + (size_t)lane * 8;
#pragma unroll
        for (int kc = 0; kc < 4; kc++) {
            uint4 u;
            u.x = h2u(o[bb][2 * kc][0] * inv0,     o[bb][2 * kc][1] * inv0);
            u.y = h2u(o[bb][2 * kc][2] * inv1,     o[bb][2 * kc][3] * inv1);
            u.z = h2u(o[bb][2 * kc + 1][0] * inv0, o[bb][2 * kc + 1][1] * inv0);
            u.w = h2u(o[bb][2 * kc + 1][2] * inv1, o[bb][2 * kc + 1][3] * inv1);
            *(uint4*)(base + (size_t)kc * 2048) = u;
        }
    }
}

// =================================================================
// Launch
// =================================================================
extern "C" void kernel_launch(void* const* d_in, const int* in_sizes, int n_in,
                              void* d_out, int out_size)
{
    const float* x  = (const float*)d_in[0];
    const float* Wq = (const float*)d_in[1];
    const float* Wk = (const float*)d_in[2];
    const float* Wv = (const float*)d_in[3];
    const float* Wo = (const float*)d_in[4];
    float* out = (float*)d_out;

    __half *Qh, *Kh, *Vh, *Ch;
    cudaGetSymbolAddress((void**)&Qh, g_Qh);
    cudaGetSymbolAddress((void**)&Kh, g_Kh);
    cudaGetSymbolAddress((void**)&Vh, g_Vh);
    cudaGetSymbolAddress((void**)&Ch, g_Ch);

    // 0: rope table
    rope_table_kernel<<<(S_LEN * 32 + 255) / 256, 256>>>();

    // 1: permute x + weights into fp16 fragment order
    int nthreads = NTOK * (D_MODEL / 4) + 4 * D_MODEL * (D_MODEL / 4);
    preround_permute_kernel<<<(nthreads + 255) / 256, 256>>>(x, Wq, Wk, Wv, Wo);

    // 2: QKV projections (fp16 mma) -> fp16 frag-order Q/K/V
    qkv_gemm_kernel<<<dim3(D_MODEL / 128, NTOK / 128, 3), 128>>>();

    // 3: fp16 attention -> fp16 A-frag-order context
    attn_f16<<<dim3(S_LEN / 128, N_HEADS, BATCH), 128>>>(Qh, Kh, Vh, Ch);

    // 4: output projection (fp16 mma) -> fp32 out
    out_gemm_kernel<<<dim3(D_MODEL / 128, NTOK / 128), 128>>>(out);
}

// round 16
// speedup vs baseline: 2.0627x; 1.1020x over previous
#include <cuda_runtime.h>
#include <cuda_fp16.h>
#include <math.h>
#include <stdint.h>

#define S_LEN    2048
#define D_MODEL  1024
#define N_HEADS  16
#define HEAD_DIM 64
#define BATCH    2
#define NTOK     (BATCH * S_LEN)   // 4096

// -------- scratch (device globals: no allocations allowed) --------
__device__ __half g_Qh[NTOK * D_MODEL];           // Q, attention A-frag order
__device__ __half g_Kh[NTOK * D_MODEL];           // K, attention B-frag order
__device__ __half g_Vh[NTOK * D_MODEL];           // V, attention B-frag order
__device__ __half g_Ch[NTOK * D_MODEL];           // ctx, out-GEMM A-frag order
__device__ __half g_Xh[NTOK * D_MODEL];           // x, GEMM A-frag order
__device__ __half g_Wh[4][D_MODEL * D_MODEL];     // weights, GEMM B-frag order
__device__ float  g_cos[S_LEN * 32];
__device__ float  g_sin[S_LEN * 32];

#define LOG2E 1.4426950408889634f

__device__ __forceinline__ unsigned h2u(float lo, float hi) {
    unsigned u;
    asm("cvt.rn.f16x2.f32 %0, %1, %2;" : "=r"(u) : "f"(hi), "f"(lo));
    return u;
}

__device__ __forceinline__ void mma16(float c[4], const unsigned a[4],
                                      unsigned b0, unsigned b1) {
    asm volatile(
        "mma.sync.aligned.m16n8k16.row.col.f32.f16.f16.f32 "
        "{%0,%1,%2,%3},{%4,%5,%6,%7},{%8,%9},{%0,%1,%2,%3};"
        : "+f"(c[0]), "+f"(c[1]), "+f"(c[2]), "+f"(c[3])
        : "r"(a[0]), "r"(a[1]), "r"(a[2]), "r"(a[3]), "r"(b0), "r"(b1));
}

// =================================================================
// Preround + permute to fp16 fragment layouts.  [R15 passing]
// =================================================================
__global__ void preround_permute_kernel(const float* __restrict__ x,
                                        const float* __restrict__ Wq,
                                        const float* __restrict__ Wk,
                                        const float* __restrict__ Wv,
                                        const float* __restrict__ Wo)
{
    const int NXq = NTOK * (D_MODEL / 4);
    const int NWq = D_MODEL * (D_MODEL / 4);
    int idx = blockIdx.x * blockDim.x + threadIdx.x;
    if (idx < NXq) {
        int m = idx >> 8, k4 = idx & 255;
        float4 v = *(const float4*)&x[(size_t)m * D_MODEL + k4 * 4];
        int m_tile = m >> 7, mrow = m & 127;
        int mt = mrow >> 4, rr = mrow & 15, g = rr & 7, rh = rr >> 3;
        int kchunk = k4 >> 2, kk0 = (k4 & 3) * 4;
        int tig0 = (kk0 & 7) >> 1;
        int id0 = (kk0 < 8 ? 0 : 4) + rh * 2;
        __half* base = g_Xh + ((size_t)(m_tile * 64 + kchunk) * 8 + mt) * 256;
        *(unsigned*)(base + (size_t)(g * 4 + tig0) * 8 + id0)     = h2u(v.x, v.y);
        *(unsigned*)(base + (size_t)(g * 4 + tig0 + 1) * 8 + id0) = h2u(v.z, v.w);
    } else if (idx < NXq + 4 * NWq) {
        int r = idx - NXq;
        int w = r / NWq; r -= w * NWq;
        int n = r >> 8, k4 = r & 255;
        const float* ws[4] = {Wq, Wk, Wv, Wo};
        float4 v = *(const float4*)&ws[w][(size_t)n * D_MODEL + k4 * 4];
        int n_tile = n >> 7, nrow = n & 127;
        int nt = nrow >> 3, g = nrow & 7;
        int kchunk = k4 >> 2, kk0 = (k4 & 3) * 4;
        int tig0 = (kk0 & 7) >> 1;
        int id0 = (kk0 < 8) ? 0 : 2;
        __half* base = g_Wh[w] + ((size_t)(n_tile * 64 + kchunk) * 16 + nt) * 128;
        *(unsigned*)(base + (size_t)(g * 4 + tig0) * 4 + id0)     = h2u(v.x, v.y);
        *(unsigned*)(base + (size_t)(g * 4 + tig0 + 1) * 4 + id0) = h2u(v.z, v.w);
    }
}

// =================================================================
// RoPE table
// =================================================================
__global__ void rope_table_kernel()
{
    int i = blockIdx.x * blockDim.x + threadIdx.x;
    if (i >= S_LEN * 32) return;
    int pos = i >> 5;
    int f   = i & 31;
    float e    = (float)(2 * f) / 64.0f;
    float pw   = powf(10000.0f, e);
    float invf = 1.0f / pw;
    float angf = (float)pos * invf;
    double s, c;
    sincos((double)angf, &s, &c);
    g_cos[i] = (float)c;
    g_sin[i] = (float)s;
}

// =================================================================
// Shared fp16 GEMM mainloop (both operands frag-order fp16).
// =================================================================
__device__ __forceinline__ void f16_gemm_main(
    const __half* __restrict__ Ag, const __half* __restrict__ Bg,
    float acc[4][8][4], __half* As, __half* Bs,
    int t, int mtb, int ntb, int lane)
{
#define LOADH(buf, s)                                                              \
    do {                                                                           \
        _Pragma("unroll")                                                          \
        for (int ii = 0; ii < 2; ii++) {                                           \
            int q = t + ii * 128;                                                  \
            unsigned da = (unsigned)__cvta_generic_to_shared(                      \
                As + (size_t)(buf) * 2048 + q * 8);                                \
            asm volatile("cp.async.cg.shared.global [%0], [%1], 16;"               \
                         :: "r"(da), "l"(Ag + (size_t)(s) * 2048 + q * 8));        \
            unsigned db = (unsigned)__cvta_generic_to_shared(                      \
                Bs + (size_t)(buf) * 2048 + q * 8);                                \
            asm volatile("cp.async.cg.shared.global [%0], [%1], 16;"               \
                         :: "r"(db), "l"(Bg + (size_t)(s) * 2048 + q * 8));        \
        }                                                                          \
        asm volatile("cp.async.commit_group;");                                    \
    } while (0)

    LOADH(0, 0);
    LOADH(1, 1);

    for (int i = 0; i < 64; i++) {
        asm volatile("cp.async.wait_group 1;");
        __syncthreads();
        if (i + 2 < 64) LOADH((i + 2) % 3, i + 2);
        const __half* Ab = As + (i % 3) * 2048;
        const __half* Bb = Bs + (i % 3) * 2048;

        unsigned af[4][4];
        uint2 bf[8];
#pragma unroll
        for (int mt = 0; mt < 4; mt++) {
            uint4 u = *(const uint4*)(Ab + (size_t)((mtb + mt) * 32 + lane) * 8);
            af[mt][0] = u.x; af[mt][1] = u.y; af[mt][2] = u.z; af[mt][3] = u.w;
        }
#pragma unroll
        for (int nt = 0; nt < 8; nt++)
            bf[nt] = *(const uint2*)(Bb + (size_t)((ntb + nt) * 32 + lane) * 4);
#pragma unroll
        for (int mt = 0; mt < 4; mt++)
#pragma unroll
            for (int nt = 0; nt < 8; nt++)
                mma16(acc[mt][nt], af[mt], bf[nt].x, bf[nt].y);
    }
#undef LOADH
}

// =================================================================
// QKV GEMM (fp16): epilogue packs Q/K/V into attention frag order.
// [R15 passing]
// =================================================================
__global__ __launch_bounds__(128, 2) void qkv_gemm_kernel()
{
    __shared__ __align__(16) __half As[3 * 2048];
    __shared__ __align__(16) __half Bs[3 * 2048];

    const int z = blockIdx.z;
    const int t = threadIdx.x, warp = t >> 5, lane = t & 31;
    const int g = lane >> 2, tig = lane & 3;
    const int mtb = (warp >> 1) * 4;
    const int ntb = (warp & 1) * 8;
    const int wm = (warp >> 1) * 64;
    const int wn = (warp & 1) * 64;
    const int mb = blockIdx.y * 128, nb = blockIdx.x * 128;

    const __half* Ag = g_Xh + (size_t)blockIdx.y * 64 * 2048;
    const __half* Bg = g_Wh[z] + (size_t)blockIdx.x * 64 * 2048;

    const int rope_mode = (z < 2) ? 1 : 0;
    const float scale = (z == 0) ? 0.125f * LOG2E : 1.0f;

    float acc[4][8][4];
#pragma unroll
    for (int mt = 0; mt < 4; mt++)
#pragma unroll
        for (int nt = 0; nt < 8; nt++)
#pragma unroll
            for (int i = 0; i < 4; i++) acc[mt][nt][i] = 0.f;

    f16_gemm_main(Ag, Bg, acc, As, Bs, t, mtb, ntb, lane);

    const int bI   = mb >> 11;
    const int qt   = (mb & 2047) >> 7;
    const int tile = ((mb & 2047) + wm) >> 6;
    const int head = (nb + wn) >> 6;
    const int bh   = bI * N_HEADS + head;

#pragma unroll
    for (int mt = 0; mt < 4; mt++) {
        float rv[8][4];
#pragma unroll
        for (int nt = 0; nt < 8; nt++) {
            float v0 = acc[mt][nt][0], v1 = acc[mt][nt][1];
            float v2 = acc[mt][nt][2], v3 = acc[mt][nt][3];
            if (rope_mode) {
                int row = mb + wm + mt * 16 + g;
                int col = nb + wn + nt * 8 + 2 * tig;
                int fi = (col & 63) >> 1;
                int p0 = row & (S_LEN - 1);
                int p1 = (row + 8) & (S_LEN - 1);
                float c0 = g_cos[p0 * 32 + fi], s0 = g_sin[p0 * 32 + fi];
                float c1 = g_cos[p1 * 32 + fi], s1 = g_sin[p1 * 32 + fi];
                float r0 = v0 * c0 - v1 * s0, r1 = v0 * s0 + v1 * c0;
                float r2 = v2 * c1 - v3 * s1, r3 = v2 * s1 + v3 * c1;
                v0 = r0 * scale; v1 = r1 * scale;
                v2 = r2 * scale; v3 = r3 * scale;
            }
            rv[nt][0] = v0; rv[nt][1] = v1; rv[nt][2] = v2; rv[nt][3] = v3;
        }

        if (z == 0) {
            int wa = 2 * (warp >> 1) + (mt >> 1), bb = mt & 1;
            __half* base = g_Qh + ((size_t)bh * 16 + qt) * 8192
                         + (size_t)((wa * 2 + bb) * 4) * 256;
#pragma unroll
            for (int j = 0; j < 4; j++) {
                uint4 u;
                u.x = h2u(rv[2 * j][0],     rv[2 * j][1]);
                u.y = h2u(rv[2 * j][2],     rv[2 * j][3]);
                u.z = h2u(rv[2 * j + 1][0], rv[2 * j + 1][1]);
                u.w = h2u(rv[2 * j + 1][2], rv[2 * j + 1][3]);
                *(uint4*)(base + (size_t)(j * 32 + lane) * 8) = u;
            }
        } else if (z == 1) {
            __half* base = g_Kh + ((size_t)bh * 32 + tile) * 4096;
#pragma unroll
            for (int j = 0; j < 4; j++) {
                uint2 lo, hi;
                lo.x = h2u(rv[2 * j][0],     rv[2 * j][1]);
                lo.y = h2u(rv[2 * j + 1][0], rv[2 * j + 1][1]);
                hi.x = h2u(rv[2 * j][2],     rv[2 * j][3]);
                hi.y = h2u(rv[2 * j + 1][2], rv[2 * j + 1][3]);
                *(uint2*)(base + (size_t)((j * 8 + 2 * mt) * 32 + lane) * 4) = lo;
                *(uint2*)(base + (size_t)((j * 8 + 2 * mt + 1) * 32 + lane) * 4) = hi;
            }
        } else {
            __half* base = g_Vh + ((size_t)bh * 32 + tile) * 4096;
            const int tk = g >> 1, b1off = (g & 1) * 2;
#pragma unroll
            for (int nt = 0; nt < 8; nt++) {
                float u0 = __shfl_xor_sync(0xffffffffu, rv[nt][0], 4);
                float u1 = __shfl_xor_sync(0xffffffffu, rv[nt][1], 4);
                float u2 = __shfl_xor_sync(0xffffffffu, rv[nt][2], 4);
                float u3 = __shfl_xor_sync(0xffffffffu, rv[nt][3], 4);
                unsigned w0, w1;
                if ((g & 1) == 0) {
                    w0 = h2u(rv[nt][0], u0);
                    w1 = h2u(rv[nt][1], u1);
                } else {
                    w0 = h2u(u2, rv[nt][2]);
                    w1 = h2u(u3, rv[nt][3]);
                }
                unsigned o0 = (unsigned)((mt * 8 + nt) * 32 + 8 * tig + tk) * 4 + b1off;
                unsigned o1 = (unsigned)((mt * 8 + nt) * 32 + 8 * tig + 4 + tk) * 4 + b1off;
                *(unsigned*)(base + o0) = w0;
                *(unsigned*)(base + o1) = w1;
            }
        }
    }
}

// =================================================================
// Output GEMM (fp16): A = g_Ch (A-frag), B = Wo (B-frag). [R15 passing]
// =================================================================
__global__ __launch_bounds__(128, 2) void out_gemm_kernel(float* __restrict__ out)
{
    __shared__ __align__(16) __half As[3 * 2048];
    __shared__ __align__(16) __half Bs[3 * 2048];

    const int t = threadIdx.x, warp = t >> 5, lane = t & 31;
    const int g = lane >> 2, tig = lane & 3;
    const int mtb = (warp >> 1) * 4;
    const int ntb = (warp & 1) * 8;
    const int wm = (warp >> 1) * 64;
    const int wn = (warp & 1) * 64;
    const int mb = blockIdx.y * 128, nb = blockIdx.x * 128;

    const __half* Ag = g_Ch + (size_t)blockIdx.y * 64 * 2048;
    const __half* Bg = g_Wh[3] + (size_t)blockIdx.x * 64 * 2048;

    float acc[4][8][4];
#pragma unroll
    for (int mt = 0; mt < 4; mt++)
#pragma unroll
        for (int nt = 0; nt < 8; nt++)
#pragma unroll
            for (int i = 0; i < 4; i++) acc[mt][nt][i] = 0.f;

    f16_gemm_main(Ag, Bg, acc, As, Bs, t, mtb, ntb, lane);

#pragma unroll
    for (int mt = 0; mt < 4; mt++) {
#pragma unroll
        for (int nt = 0; nt < 8; nt++) {
            int row = mb + wm + mt * 16 + g;
            int col = nb + wn + nt * 8 + 2 * tig;
            *(float2*)&out[(size_t)row * D_MODEL + col] =
                make_float2(acc[mt][nt][0], acc[mt][nt][1]);
            *(float2*)&out[(size_t)(row + 8) * D_MODEL + col] =
                make_float2(acc[mt][nt][2], acc[mt][nt][3]);
        }
    }
}

// =================================================================
// FP16 flash attention, causal. PAIRED-TILE schedule: each CTA does
// q-tile j (light) then q-tile 15-j (heavy) -> uniform 17 k-iters
// per CTA, 256 CTAs = one balanced wave.
// =================================================================
__global__ __launch_bounds__(128, 2) void attn_f16(
    const __half* __restrict__ Qf, const __half* __restrict__ Kf,
    const __half* __restrict__ Vf, __half* __restrict__ Ch)
{
    __shared__ __align__(16) __half Ksf[4096];
    __shared__ __align__(16) __half Vsf[4096];

    const int t = threadIdx.x, warp = t >> 5, lane = t & 31;
    const int g = lane >> 2, tig = lane & 3;
    const int h  = blockIdx.y, b = blockIdx.z;
    const int w32 = warp * 32;
    const int bh = b * N_HEADS + h;
    const int NTILES = S_LEN / 128;      // 16

    for (int pass = 0; pass < 2; pass++) {
        const int tileI = pass == 0 ? (int)blockIdx.x
                                    : (NTILES - 1 - (int)blockIdx.x);
        const int qb = tileI * 128;

        // ---- Q A-fragments: direct coalesced uint4 loads ----
        const __half* Qblk = Qf + ((size_t)bh * 16 + tileI) * 8192;
        unsigned qf[2][4][4];
#pragma unroll
        for (int bb = 0; bb < 2; bb++)
#pragma unroll
            for (int kc = 0; kc < 4; kc++) {
                uint4 u = *(const uint4*)(Qblk +
                    (size_t)(((warp * 2 + bb) * 4 + kc) * 32 + lane) * 8);
                qf[bb][kc][0] = u.x; qf[bb][kc][1] = u.y;
                qf[bb][kc][2] = u.z; qf[bb][kc][3] = u.w;
            }

        float m_[2][2], l_[2][2];
        float o[2][8][4];
#pragma unroll
        for (int bb = 0; bb < 2; bb++) {
            m_[bb][0] = -1e30f; m_[bb][1] = -1e30f;
            l_[bb][0] = 0.f;    l_[bb][1] = 0.f;
#pragma unroll
            for (int nt = 0; nt < 8; nt++)
#pragma unroll
                for (int i = 0; i < 4; i++) o[bb][nt][i] = 0.f;
        }

        const int wrow_max = qb + w32 + 31;

        for (int kt = 0; kt <= qb + 64; kt += 64) {
            __syncthreads();   // prev Ksf/Vsf reads complete (both passes)
            const uint4* Kg = (const uint4*)(Kf + ((size_t)bh * 32 + (kt >> 6)) * 4096);
            const uint4* Vg = (const uint4*)(Vf + ((size_t)bh * 32 + (kt >> 6)) * 4096);
#pragma unroll
            for (int i = 0; i < 4; i++) {
                ((uint4*)Ksf)[t + i * 128] = Kg[t + i * 128];
                ((uint4*)Vsf)[t + i * 128] = Vg[t + i * 128];
            }
            __syncthreads();

            if (kt > wrow_max) continue;

            float s[2][8][4];
#pragma unroll
            for (int nt = 0; nt < 8; nt++) {
                float c0[4] = {0.f, 0.f, 0.f, 0.f};
                float c1[4] = {0.f, 0.f, 0.f, 0.f};
#pragma unroll
                for (int kc = 0; kc < 4; kc++) {
                    uint2 kb = *(const uint2*)(Ksf + (size_t)((kc * 8 + nt) * 32 + lane) * 4);
                    mma16(c0, qf[0][kc], kb.x, kb.y);
                    mma16(c1, qf[1][kc], kb.x, kb.y);
                }
#pragma unroll
                for (int i = 0; i < 4; i++) { s[0][nt][i] = c0[i]; s[1][nt][i] = c1[i]; }
            }

#pragma unroll
            for (int bb = 0; bb < 2; bb++) {
                const int r0 = qb + w32 + bb * 16 + g;
                const int r1 = r0 + 8;
                if (kt + 63 > qb + w32 + bb * 16) {
#pragma unroll
                    for (int nt = 0; nt < 8; nt++) {
                        int k0 = kt + nt * 8 + 2 * tig;
                        if (k0 > r0)     s[bb][nt][0] = -1e30f;
                        if (k0 + 1 > r0) s[bb][nt][1] = -1e30f;
                        if (k0 > r1)     s[bb][nt][2] = -1e30f;
                        if (k0 + 1 > r1) s[bb][nt][3] = -1e30f;
                    }
                }

                float mx0 = -1e30f, mx1 = -1e30f;
#pragma unroll
                for (int nt = 0; nt < 8; nt++) {
                    mx0 = fmaxf(mx0, fmaxf(s[bb][nt][0], s[bb][nt][1]));
                    mx1 = fmaxf(mx1, fmaxf(s[bb][nt][2], s[bb][nt][3]));
                }
                mx0 = fmaxf(mx0, __shfl_xor_sync(0xffffffffu, mx0, 1));
                mx0 = fmaxf(mx0, __shfl_xor_sync(0xffffffffu, mx0, 2));
                mx1 = fmaxf(mx1, __shfl_xor_sync(0xffffffffu, mx1, 1));
                mx1 = fmaxf(mx1, __shfl_xor_sync(0xffffffffu, mx1, 2));

                float nm0 = fmaxf(m_[bb][0], mx0), nm1 = fmaxf(m_[bb][1], mx1);
                float a0 = exp2f(m_[bb][0] - nm0), a1 = exp2f(m_[bb][1] - nm1);
                float sum0 = 0.f, sum1 = 0.f;
#pragma unroll
                for (int nt = 0; nt < 8; nt++) {
                    s[bb][nt][0] = exp2f(s[bb][nt][0] - nm0);
                    s[bb][nt][1] = exp2f(s[bb][nt][1] - nm0);
                    s[bb][nt][2] = exp2f(s[bb][nt][2] - nm1);
                    s[bb][nt][3] = exp2f(s[bb][nt][3] - nm1);
                    sum0 += s[bb][nt][0] + s[bb][nt][1];
                    sum1 += s[bb][nt][2] + s[bb][nt][3];
                }
                sum0 += __shfl_xor_sync(0xffffffffu, sum0, 1);
                sum0 += __shfl_xor_sync(0xffffffffu, sum0, 2);
                sum1 += __shfl_xor_sync(0xffffffffu, sum1, 1);
                sum1 += __shfl_xor_sync(0xffffffffu, sum1, 2);

                l_[bb][0] = l_[bb][0] * a0 + sum0;
                l_[bb][1] = l_[bb][1] * a1 + sum1;
                m_[bb][0] = nm0; m_[bb][1] = nm1;
#pragma unroll
                for (int nt = 0; nt < 8; nt++) {
                    o[bb][nt][0] *= a0; o[bb][nt][1] *= a0;
                    o[bb][nt][2] *= a1; o[bb][nt][3] *= a1;
                }
            }

#pragma unroll
            for (int kcp = 0; kcp < 4; kcp++) {
                unsigned pa[2][4];
#pragma unroll
                for (int bb = 0; bb < 2; bb++) {
                    pa[bb][0] = h2u(s[bb][2 * kcp][0],     s[bb][2 * kcp][1]);
                    pa[bb][1] = h2u(s[bb][2 * kcp][2],     s[bb][2 * kcp][3]);
                    pa[bb][2] = h2u(s[bb][2 * kcp + 1][0], s[bb][2 * kcp + 1][1]);
                    pa[bb][3] = h2u(s[bb][2 * kcp + 1][2], s[bb][2 * kcp + 1][3]);
                }
#pragma unroll
                for (int nt = 0; nt < 8; nt++) {
                    uint2 vb = *(const uint2*)(Vsf + (size_t)((kcp * 8 + nt) * 32 + lane) * 4);
                    mma16(o[0][nt], pa[0], vb.x, vb.y);
                    mma16(o[1][nt], pa[1], vb.x, vb.y);
                }
            }
        }

        // ---- epilogue: normalize, pack to out-GEMM A-frag order ----
        const int m_tile = (b * S_LEN + qb) >> 7;
#pragma unroll
        for (int bb = 0; bb < 2; bb++) {
            float inv0 = 1.0f / l_[bb][0], inv1 = 1.0f / l_[bb][1];
            const int mt = warp * 2 + bb;
            __half* base = g_Ch + ((size_t)(m_tile * 64 + h * 4) * 8 + mt) * 256
                         + (size_t)lane * 8;
#pragma unroll
            for (int kc = 0; kc < 4; kc++) {
                uint4 u;
                u.x = h2u(o[bb][2 * kc][0] * inv0,     o[bb][2 * kc][1] * inv0);
                u.y = h2u(o[bb][2 * kc][2] * inv1,     o[bb][2 * kc][3] * inv1);
                u.z = h2u(o[bb][2 * kc + 1][0] * inv0, o[bb][2 * kc + 1][1] * inv0);
                u.w = h2u(o[bb][2 * kc + 1][2] * inv1, o[bb][2 * kc + 1][3] * inv1);
                *(uint4*)(base + (size_t)kc * 2048) = u;
            }
        }
    }
}

// =================================================================
// Launch
// =================================================================
extern "C" void kernel_launch(void* const* d_in, const int* in_sizes, int n_in,
                              void* d_out, int out_size)
{
    const float* x  = (const float*)d_in[0];
    const float* Wq = (const float*)d_in[1];
    const float* Wk = (const float*)d_in[2];
    const float* Wv = (const float*)d_in[3];
    const float* Wo = (const float*)d_in[4];
    float* out = (float*)d_out;

    __half *Qh, *Kh, *Vh, *Ch;
    cudaGetSymbolAddress((void**)&Qh, g_Qh);
    cudaGetSymbolAddress((void**)&Kh, g_Kh);
    cudaGetSymbolAddress((void**)&Vh, g_Vh);
    cudaGetSymbolAddress((void**)&Ch, g_Ch);

    // 0: rope table
    rope_table_kernel<<<(S_LEN * 32 + 255) / 256, 256>>>();

    // 1: permute x + weights into fp16 fragment order
    int nthreads = NTOK * (D_MODEL / 4) + 4 * D_MODEL * (D_MODEL / 4);
    preround_permute_kernel<<<(nthreads + 255) / 256, 256>>>(x, Wq, Wk, Wv, Wo);

    // 2: QKV projections (fp16 mma) -> fp16 frag-order Q/K/V
    qkv_gemm_kernel<<<dim3(D_MODEL / 128, NTOK / 128, 3), 128>>>();

    // 3: fp16 attention, paired-tile balanced schedule (256 CTAs)
    attn_f16<<<dim3(S_LEN / 256, N_HEADS, BATCH), 128>>>(Qh, Kh, Vh, Ch);

    // 4: output projection (fp16 mma) -> fp32 out
    out_gemm_kernel<<<dim3(D_MODEL / 128, NTOK / 128), 128>>>(out);
}